// round 9
// baseline (speedup 1.0000x reference)
#include <cuda_runtime.h>
#include <math.h>
#include <stdint.h>

#define BB  4
#define SS  256
#define VV  64
#define HH  128
#define NHH 8
#define DHH 16
#define NLL 3
#define LLP1 11
#define MM  (BB*SS)   // 1024
#define KAB 96        // padded causal K (64 A + 11 Bl + 21 zero)

// -------- device scratch (static; allocation-free) --------
__device__ float g_adj[VV*VV*LLP1];
__device__ float g_Z1[(size_t)VV*MM*HH];
__device__ float g_Z2[(size_t)VV*MM*HH];
__device__ float g_Qb[(size_t)VV*MM*HH];
__device__ float g_Kb[(size_t)VV*MM*HH];
__device__ float g_AB[(size_t)VV*KAB*MM];   // k-major: [v][k][m]
__device__ float g_Wc[KAB*HH];
__device__ float g_weff[VV*HH];
__device__ float g_beff[VV];
__device__ float g_Wvy[(size_t)VV*HH*NHH];  // [v][h*8+n]
__device__ float g_cy[VV*NHH];
__device__ float g_Y8[(size_t)NHH*VV*MM];   // [n][v][m]
__device__ float g_P[(size_t)NHH*VV*MM];    // per-head partial outputs [n][v][m]

__device__ __forceinline__ float* buf_sel(int s) {
    return (s == 0) ? g_Z1 : (s == 1) ? g_Z2 : (s == 2) ? g_Qb
         : (s == 3) ? g_Kb : g_AB;
}

__device__ __forceinline__ void cpasync16(uint32_t saddr, const void* g) {
    asm volatile("cp.async.cg.shared.global [%0], [%1], 16;\n" :: "r"(saddr), "l"(g));
}

// -------- sigmoid of adjacency logits --------
__global__ void sigmoid_adj_kernel(const float* __restrict__ logits) {
    int idx = blockIdx.x * blockDim.x + threadIdx.x;
    if (idx < VV*VV*LLP1) {
        float v = logits[idx];
        g_adj[idx] = 1.f / (1.f + expf(-v));
    }
}

// -------- build shared causal weight Wc[96][128] = [var_emb; temp_emb; 0] --------
__global__ void build_Wc_kernel(const float* __restrict__ var_emb,
                                const float* __restrict__ temp_emb) {
    int idx = blockIdx.x * 256 + threadIdx.x;
    if (idx >= KAB*HH) return;
    int r = idx >> 7, h = idx & 127;
    float val = 0.f;
    if (r < VV) val = var_emb[r*HH + h];
    else if (r < VV + LLP1) val = temp_emb[(r - VV)*HH + h];
    g_Wc[idx] = val;
}

// -------- fold O-proj into output head: weff[v]=Wo[v]@outW[v], beff[v]=bo.outW+outb --------
__global__ void build_weff_kernel(const float* __restrict__ Wo,
                                  const float* __restrict__ bo,
                                  const float* __restrict__ outW,
                                  const float* __restrict__ outb) {
    const int v = blockIdx.x;
    const int h = threadIdx.x;   // 128
    __shared__ float sw[HH];
    __shared__ float red[HH];
    sw[h] = outW[v*HH + h];
    __syncthreads();
    const float* wp = Wo + ((size_t)v*HH + h)*HH;
    float s = 0.f;
    #pragma unroll 8
    for (int k = 0; k < HH; k++) s = fmaf(wp[k], sw[k], s);
    g_weff[v*HH + h] = s;
    red[h] = bo[v*HH + h] * sw[h];
    __syncthreads();
    #pragma unroll
    for (int o = 64; o > 0; o >>= 1) {
        if (h < o) red[h] += red[h + o];
        __syncthreads();
    }
    if (h == 0) g_beff[v] = red[0] + outb[v];
}

// -------- fold V-proj through the head; grid (V, 4), one output per thread --------
__global__ void build_Wvy_kernel(const float* __restrict__ Wv,
                                 const float* __restrict__ bv) {
    const int v = blockIdx.x;
    const int q = blockIdx.y;
    const int t = threadIdx.x;   // 256
    __shared__ float wsh[HH];
    if (t < HH) wsh[t] = g_weff[v*HH + t];
    __syncthreads();
    const int e = q*256 + t;     // e = h*8 + n
    const int h = e >> 3, n = e & 7;
    const float* wp = Wv + ((size_t)v*HH + h)*HH + n*DHH;
    const float* gp = wsh + n*DHH;
    float4 x0 = *(const float4*)(wp),   x1 = *(const float4*)(wp+4);
    float4 x2 = *(const float4*)(wp+8), x3 = *(const float4*)(wp+12);
    float4 g0 = *(const float4*)(gp),   g1 = *(const float4*)(gp+4);
    float4 g2 = *(const float4*)(gp+8), g3 = *(const float4*)(gp+12);
    float s0 = x0.x*g0.x + x0.y*g0.y + x0.z*g0.z + x0.w*g0.w;
    float s1 = x1.x*g1.x + x1.y*g1.y + x1.z*g1.z + x1.w*g1.w;
    float s2 = x2.x*g2.x + x2.y*g2.y + x2.z*g2.z + x2.w*g2.w;
    float s3 = x3.x*g3.x + x3.y*g3.y + x3.z*g3.z + x3.w*g3.w;
    g_Wvy[(size_t)v*HH*NHH + e] = (s0 + s1) + (s2 + s3);
    if (q == 0 && t < NHH) {
        const float* bp = bv + (size_t)v*HH + t*DHH;
        const float* gp2 = wsh + t*DHH;
        float s = 0.f;
        #pragma unroll
        for (int d = 0; d < DHH; d++) s = fmaf(bp[d], gp2[d], s);
        g_cy[v*NHH + t] = s;
    }
}

// -------- stage AB_T[i][k][m]; 256 threads: s-range split in half --------
__global__ void __launch_bounds__(256) build_AB_kernel(const float* __restrict__ x) {
    const int i  = blockIdx.x;
    const int b  = blockIdx.y;
    const int t0 = blockIdx.z * 128;
    __shared__ float xsh[VV][140];
    __shared__ float adjs[VV][12];
    __shared__ float blsh[LLP1][129];
    const int tid = threadIdx.x;     // 256

    for (int f = tid; f < 138*16; f += 256) {
        int j = f >> 4, s4 = f & 15;
        int t = t0 - 10 + j;
        float4 xv = make_float4(0.f, 0.f, 0.f, 0.f);
        if (t >= 0) xv = *(const float4*)(x + ((size_t)(b*SS + t))*VV + s4*4);
        xsh[s4*4+0][j] = xv.x;
        xsh[s4*4+1][j] = xv.y;
        xsh[s4*4+2][j] = xv.z;
        xsh[s4*4+3][j] = xv.w;
    }
    for (int f = tid; f < VV*LLP1; f += 256) {
        int s = f / LLP1, l = f - s*LLP1;
        adjs[s][l] = g_adj[((size_t)s*VV + i)*LLP1 + l];
    }
    __syncthreads();

    const int t    = tid & 127;
    const int half = tid >> 7;
    const int j0 = t + 10;
    float bl[LLP1];
    #pragma unroll
    for (int l = 0; l < LLP1; l++) bl[l] = 0.f;

    float* ABi = g_AB + (size_t)i*KAB*MM + b*SS + t0;
    const int s0 = half*32;
    #pragma unroll 2
    for (int s = s0; s < s0 + 32; s++) {
        const float* xr = xsh[s];
        const float* ar = adjs[s];
        float a = 0.f;
        #pragma unroll
        for (int l = 0; l < LLP1; l++) {
            float p = xr[j0 - l] * ar[l];
            a += p;
            bl[l] += p;
        }
        ABi[(size_t)s*MM + t] = a;
    }
    if (half == 1) {
        #pragma unroll
        for (int l = 0; l < LLP1; l++) blsh[l][t] = bl[l];
    }
    __syncthreads();
    if (half == 0) {
        #pragma unroll
        for (int l = 0; l < LLP1; l++) ABi[(size_t)(VV + l)*MM + t] = bl[l] + blsh[l][t];
    } else {
        #pragma unroll
        for (int r = VV + LLP1; r < KAB; r++) ABi[(size_t)r*MM + t] = 0.f;
    }
}

// -------- batched per-variable GEMM: 128x128 tile, KT=16, double-buffered --------
// warp owns 16 rows x 128 cols; lane owns 4 cols. Per kk: 5 LDS.128 + 64 FFMA.
// MODE 0: bias + LayerNorm + exact GELU   MODE 1: bias   MODE 2: plain
template<int MODE, int KDIM, bool XT, bool SHW>
__global__ void __launch_bounds__(256, 2)
gemm3(int src, int dst,
      const float* __restrict__ Wall, const float* __restrict__ ball,
      const float* __restrict__ lng, const float* __restrict__ lnb, int li)
{
    constexpr int NK = KDIM / 16;
    __shared__ float As[2][16][128];   // 16 KB
    __shared__ float Bs[2][16][128];   // 16 KB
    const uint32_t As_u = (uint32_t)__cvta_generic_to_shared(&As[0][0][0]);
    const uint32_t Bs_u = (uint32_t)__cvta_generic_to_shared(&Bs[0][0][0]);

    const int v   = blockIdx.y;
    const int m0  = blockIdx.x * 128;
    const int tid = threadIdx.x;
    const int w = tid >> 5, lane = tid & 31;

    const float* Xb = buf_sel(src);
    const float* Xv = XT ? (Xb + (size_t)v*KDIM*MM)
                         : (Xb + ((size_t)v*MM + m0)*KDIM);
    const float* Wv = SHW ? g_Wc
                    : (MODE == 0 ? Wall + ((size_t)v*NLL + li)*HH*HH
                                 : Wall + (size_t)v*HH*HH);

    float acc[16][4];
    #pragma unroll
    for (int r = 0; r < 16; r++) { acc[r][0]=0.f; acc[r][1]=0.f; acc[r][2]=0.f; acc[r][3]=0.f; }

    const int am = tid >> 1, kseg = tid & 1;    // !XT A loader
    const int xkr = tid >> 4, xms = tid & 15;   // XT A loader + B loader
    float4 pa0, pa1;

    auto issueA = [&](int k0, int buf) {
        if (XT) {
            const float* g = Xv + (size_t)(k0 + xkr)*MM + m0 + xms*8;
            uint32_t d = As_u + (uint32_t)((buf*2048 + xkr*128 + xms*8) * 4);
            cpasync16(d, g);
            cpasync16(d + 16, g + 4);
        } else {
            const float* g = Xv + (size_t)am*KDIM + k0 + kseg*8;
            pa0 = *(const float4*)g;
            pa1 = *(const float4*)(g + 4);
        }
    };
    auto storeA = [&](int buf) {
        if (!XT) {
            float* base = &As[buf][0][0] + am;
            base[(kseg*8+0)*128] = pa0.x; base[(kseg*8+1)*128] = pa0.y;
            base[(kseg*8+2)*128] = pa0.z; base[(kseg*8+3)*128] = pa0.w;
            base[(kseg*8+4)*128] = pa1.x; base[(kseg*8+5)*128] = pa1.y;
            base[(kseg*8+6)*128] = pa1.z; base[(kseg*8+7)*128] = pa1.w;
        }
    };
    auto issueB = [&](int k0, int buf) {
        const float* g = Wv + (size_t)(k0 + xkr)*HH + xms*8;
        uint32_t d = Bs_u + (uint32_t)((buf*2048 + xkr*128 + xms*8) * 4);
        cpasync16(d, g);
        cpasync16(d + 16, g + 4);
    };

    issueA(0, 0);
    issueB(0, 0);
    storeA(0);
    asm volatile("cp.async.commit_group;\n");
    asm volatile("cp.async.wait_group 0;\n" ::: "memory");
    __syncthreads();

    #pragma unroll 1
    for (int kt = 0; kt < NK; kt++) {
        const int cur = kt & 1, nxt = cur ^ 1;
        if (kt + 1 < NK) {
            issueA((kt + 1)*16, nxt);
            issueB((kt + 1)*16, nxt);
            asm volatile("cp.async.commit_group;\n");
        }
        const float* Ap = &As[cur][0][0] + w*16;
        const float* Bp = &Bs[cur][0][0] + (lane << 2);
        #pragma unroll 4
        for (int kk = 0; kk < 16; kk++) {
            float4 a0 = *(const float4*)(Ap + kk*128);
            float4 a1 = *(const float4*)(Ap + kk*128 + 4);
            float4 a2 = *(const float4*)(Ap + kk*128 + 8);
            float4 a3 = *(const float4*)(Ap + kk*128 + 12);
            float4 b  = *(const float4*)(Bp + kk*128);
            float ar[16] = {a0.x,a0.y,a0.z,a0.w, a1.x,a1.y,a1.z,a1.w,
                            a2.x,a2.y,a2.z,a2.w, a3.x,a3.y,a3.z,a3.w};
            #pragma unroll
            for (int r = 0; r < 16; r++) {
                acc[r][0] = fmaf(ar[r], b.x, acc[r][0]);
                acc[r][1] = fmaf(ar[r], b.y, acc[r][1]);
                acc[r][2] = fmaf(ar[r], b.z, acc[r][2]);
                acc[r][3] = fmaf(ar[r], b.w, acc[r][3]);
            }
        }
        if (kt + 1 < NK) {
            storeA(nxt);
            asm volatile("cp.async.wait_group 0;\n" ::: "memory");
            __syncthreads();
        }
    }

    if (MODE < 2) {
        const float* bvp = (MODE == 0) ? ball + ((size_t)v*NLL + li)*HH
                                       : ball + (size_t)v*HH;
        float4 bias = *(const float4*)(bvp + lane*4);
        #pragma unroll
        for (int r = 0; r < 16; r++) {
            acc[r][0] += bias.x; acc[r][1] += bias.y;
            acc[r][2] += bias.z; acc[r][3] += bias.w;
        }
    }

    if (MODE == 0) {
        const float* gp = lng + ((size_t)v*NLL + li)*HH;
        const float* bp = lnb + ((size_t)v*NLL + li)*HH;
        float4 gv4 = *(const float4*)(gp + lane*4);
        float4 bv4 = *(const float4*)(bp + lane*4);
        float gg[4] = {gv4.x, gv4.y, gv4.z, gv4.w};
        float bt[4] = {bv4.x, bv4.y, bv4.z, bv4.w};
        #pragma unroll
        for (int r = 0; r < 16; r++) {
            float s1 = acc[r][0] + acc[r][1] + acc[r][2] + acc[r][3];
            float s2 = acc[r][0]*acc[r][0] + acc[r][1]*acc[r][1]
                     + acc[r][2]*acc[r][2] + acc[r][3]*acc[r][3];
            #pragma unroll
            for (int o = 16; o > 0; o >>= 1) {
                s1 += __shfl_xor_sync(0xffffffffu, s1, o);
                s2 += __shfl_xor_sync(0xffffffffu, s2, o);
            }
            float mu  = s1 * (1.f/128.f);
            float var = s2 * (1.f/128.f) - mu*mu;
            float inv = rsqrtf(var + 1e-5f);
            #pragma unroll
            for (int c = 0; c < 4; c++) {
                float xx = (acc[r][c] - mu) * inv * gg[c] + bt[c];
                acc[r][c] = 0.5f * xx * (1.f + erff(xx * 0.70710678118654752f));
            }
        }
    }

    float* Yv = buf_sel(dst) + ((size_t)v*MM + m0)*HH;
    #pragma unroll
    for (int r = 0; r < 16; r++) {
        float4 st = make_float4(acc[r][0], acc[r][1], acc[r][2], acc[r][3]);
        *(float4*)(Yv + (size_t)(w*16 + r)*HH + lane*4) = st;
    }
}

// -------- y8: Y8[n][v][m] = Z2[v,m,:].Wvy[v,:,n] + cy[v,n] --------
__global__ void __launch_bounds__(256) y8_kernel() {
    const int v = blockIdx.x, b = blockIdx.y;
    __shared__ __align__(16) float wv_sh[HH][NHH];   // 4 KB
    const int t = threadIdx.x;
    {
        const float4* src = (const float4*)(g_Wvy + (size_t)v*HH*NHH);
        float4* dst = (float4*)&wv_sh[0][0];
        dst[t] = src[t];
    }
    __syncthreads();

    const float* zr = g_Z2 + ((size_t)v*MM + (size_t)b*SS + t)*HH;
    float ya[NHH];
    #pragma unroll
    for (int n = 0; n < NHH; n++) ya[n] = g_cy[v*NHH + n];
    #pragma unroll 4
    for (int h0 = 0; h0 < HH; h0 += 4) {
        float4 z = *(const float4*)(zr + h0);
        const float zz[4] = {z.x, z.y, z.z, z.w};
        #pragma unroll
        for (int hi = 0; hi < 4; hi++) {
            float4 w0 = *(const float4*)&wv_sh[h0 + hi][0];
            float4 w1 = *(const float4*)&wv_sh[h0 + hi][4];
            ya[0] = fmaf(zz[hi], w0.x, ya[0]);
            ya[1] = fmaf(zz[hi], w0.y, ya[1]);
            ya[2] = fmaf(zz[hi], w0.z, ya[2]);
            ya[3] = fmaf(zz[hi], w0.w, ya[3]);
            ya[4] = fmaf(zz[hi], w1.x, ya[4]);
            ya[5] = fmaf(zz[hi], w1.y, ya[5]);
            ya[6] = fmaf(zz[hi], w1.z, ya[6]);
            ya[7] = fmaf(zz[hi], w1.w, ya[7]);
        }
    }
    const size_t mo = (size_t)v*MM + (size_t)b*SS + t;
    #pragma unroll
    for (int n = 0; n < NHH; n++) g_Y8[(size_t)n*VV*MM + mo] = ya[n];
}

// -------- attention: per-(head,v,b) block, one query/thread, scalar-y online softmax --------
__global__ void __launch_bounds__(256) attn3_kernel() {
    const int n = blockIdx.x, v = blockIdx.y, b = blockIdx.z;
    __shared__ __align__(16) float Ks[SS][DHH];   // 16 KB
    __shared__ float ys[SS];                      // 1 KB

    const int t = threadIdx.x;
    const size_t base = ((size_t)v*MM + (size_t)b*SS)*HH + n*DHH;
    const size_t mo = (size_t)v*MM + (size_t)b*SS + t;
    {
        const float* Kp = g_Kb + base + (size_t)t*HH;
        *(float4*)&Ks[t][0]  = *(const float4*)(Kp);
        *(float4*)&Ks[t][4]  = *(const float4*)(Kp + 4);
        *(float4*)&Ks[t][8]  = *(const float4*)(Kp + 8);
        *(float4*)&Ks[t][12] = *(const float4*)(Kp + 12);
        ys[t] = g_Y8[(size_t)n*VV*MM + mo];
    }

    const float* Qp = g_Qb + base + (size_t)t*HH;
    float4 q0 = *(const float4*)(Qp);
    float4 q1 = *(const float4*)(Qp + 4);
    float4 q2 = *(const float4*)(Qp + 8);
    float4 q3 = *(const float4*)(Qp + 12);
    const float sc = 0.25f;   // 1/sqrt(DH)
    q0.x*=sc; q0.y*=sc; q0.z*=sc; q0.w*=sc;
    q1.x*=sc; q1.y*=sc; q1.z*=sc; q1.w*=sc;
    q2.x*=sc; q2.y*=sc; q2.z*=sc; q2.w*=sc;
    q3.x*=sc; q3.y*=sc; q3.z*=sc; q3.w*=sc;
    __syncthreads();

    float mx = -3.0e38f, lsum = 0.f, acc = 0.f;

    #pragma unroll 2
    for (int j = 0; j < SS; j += 2) {
        const float4* kr0 = (const float4*)Ks[j];
        const float4* kr1 = (const float4*)Ks[j+1];
        float4 ka0=kr0[0], ka1=kr0[1], ka2=kr0[2], ka3=kr0[3];
        float4 kb0=kr1[0], kb1=kr1[1], kb2=kr1[2], kb3=kr1[3];
        float sa = ((q0.x*ka0.x + q0.y*ka0.y) + (q0.z*ka0.z + q0.w*ka0.w))
                 + ((q1.x*ka1.x + q1.y*ka1.y) + (q1.z*ka1.z + q1.w*ka1.w))
                 + ((q2.x*ka2.x + q2.y*ka2.y) + (q2.z*ka2.z + q2.w*ka2.w))
                 + ((q3.x*ka3.x + q3.y*ka3.y) + (q3.z*ka3.z + q3.w*ka3.w));
        float sb = ((q0.x*kb0.x + q0.y*kb0.y) + (q0.z*kb0.z + q0.w*kb0.w))
                 + ((q1.x*kb1.x + q1.y*kb1.y) + (q1.z*kb1.z + q1.w*kb1.w))
                 + ((q2.x*kb2.x + q2.y*kb2.y) + (q2.z*kb2.z + q2.w*kb2.w))
                 + ((q3.x*kb3.x + q3.y*kb3.y) + (q3.z*kb3.z + q3.w*kb3.w));
        float mn = fmaxf(sa, sb);
        if (mn > mx) {
            float f = __expf(mx - mn);
            lsum *= f;
            acc  *= f;
            mx = mn;
        }
        float pa = __expf(sa - mx);
        float pb = __expf(sb - mx);
        float2 y2 = *(const float2*)&ys[j];
        lsum += pa + pb;
        acc = fmaf(pa, y2.x, fmaf(pb, y2.y, acc));
    }

    g_P[(size_t)n*VV*MM + mo] = acc / lsum;
}

// -------- reduce heads + beff -> out[m][v] --------
__global__ void reduce_kernel(float* __restrict__ out) {
    const int e = blockIdx.x * 256 + threadIdx.x;   // e = v*MM + m
    if (e >= VV*MM) return;
    const int v = e >> 10;
    const int m = e & 1023;
    float s = g_beff[v];
    #pragma unroll
    for (int n = 0; n < NHH; n++) s += g_P[(size_t)n*VV*MM + e];
    out[(size_t)m*VV + v] = s;
}

extern "C" void kernel_launch(void* const* d_in, const int* in_sizes, int n_in,
                              void* d_out, int out_size) {
    const float* x        = (const float*)d_in[0];
    const float* adjl     = (const float*)d_in[1];
    const float* var_emb  = (const float*)d_in[2];
    const float* temp_emb = (const float*)d_in[3];
    const float* mech_W   = (const float*)d_in[4];
    const float* mech_b   = (const float*)d_in[5];
    const float* ln_g     = (const float*)d_in[6];
    const float* ln_b     = (const float*)d_in[7];
    const float* Wq       = (const float*)d_in[8];
    const float* Wk       = (const float*)d_in[9];
    const float* Wv       = (const float*)d_in[10];
    const float* Wo       = (const float*)d_in[11];
    const float* bq       = (const float*)d_in[12];
    const float* bk       = (const float*)d_in[13];
    const float* bv       = (const float*)d_in[14];
    const float* bo       = (const float*)d_in[15];
    const float* out_W    = (const float*)d_in[16];
    const float* out_b    = (const float*)d_in[17];
    float* out = (float*)d_out;

    sigmoid_adj_kernel<<<(VV*VV*LLP1 + 255)/256, 256>>>(adjl);
    build_Wc_kernel<<<(KAB*HH + 255)/256, 256>>>(var_emb, temp_emb);
    build_weff_kernel<<<VV, 128>>>(Wo, bo, out_W, out_b);
    build_Wvy_kernel<<<dim3(VV, 4), 256>>>(Wv, bv);
    build_AB_kernel<<<dim3(VV, BB, 2), 256>>>(x);

    // causal z = AB @ Wc  -> Z1
    gemm3<2,KAB,true,true><<<dim3(8, VV), 256>>>(4, 0, nullptr, nullptr, nullptr, nullptr, 0);

    // mech layers: Z1 -> Z2 -> Z1 -> Z2
    gemm3<0,128,false,false><<<dim3(8, VV), 256>>>(0, 1, mech_W, mech_b, ln_g, ln_b, 0);
    gemm3<0,128,false,false><<<dim3(8, VV), 256>>>(1, 0, mech_W, mech_b, ln_g, ln_b, 1);
    gemm3<0,128,false,false><<<dim3(8, VV), 256>>>(0, 1, mech_W, mech_b, ln_g, ln_b, 2);

    // folded V path: Y8 = Z2 @ Wvy + cy
    y8_kernel<<<dim3(VV, BB), 256>>>();

    // Q/K projections from Z2
    gemm3<1,128,false,false><<<dim3(8, VV), 256>>>(1, 2, Wq, bq, nullptr, nullptr, 0);
    gemm3<1,128,false,false><<<dim3(8, VV), 256>>>(1, 3, Wk, bk, nullptr, nullptr, 0);

    // attention partials per head
    attn3_kernel<<<dim3(NHH, VV, BB), 256>>>();

    // sum heads + bias -> out
    reduce_kernel<<<(VV*MM + 255)/256, 256>>>(out);
}

// round 10
// speedup vs baseline: 1.1239x; 1.1239x over previous
#include <cuda_runtime.h>
#include <math.h>
#include <stdint.h>

#define BB  4
#define SS  256
#define VV  64
#define HH  128
#define NHH 8
#define DHH 16
#define NLL 3
#define LLP1 11
#define MM  (BB*SS)   // 1024
#define KAB 96        // padded causal K (64 A + 11 Bl + 21 zero)

// -------- device scratch (static; allocation-free) --------
__device__ float g_adj[VV*VV*LLP1];
__device__ float g_Z1[(size_t)VV*MM*HH];
__device__ float g_Z2[(size_t)VV*MM*HH];
__device__ float g_Qb[(size_t)VV*MM*HH];
__device__ float g_Kb[(size_t)VV*MM*HH];
__device__ float g_AB[(size_t)VV*KAB*MM];   // k-major: [v][k][m]
__device__ float g_Wc[KAB*HH];
__device__ float g_weff[VV*HH];
__device__ float g_beff[VV];
__device__ float g_Wvy[(size_t)VV*HH*NHH];  // [v][h*8+n]
__device__ float g_cy[VV*NHH];
__device__ float g_Y8[(size_t)NHH*VV*MM];   // [n][v][m]
__device__ float g_P[(size_t)NHH*VV*MM];    // per-head partial outputs [n][v][m]

__device__ __forceinline__ float* buf_sel(int s) {
    return (s == 0) ? g_Z1 : (s == 1) ? g_Z2 : (s == 2) ? g_Qb
         : (s == 3) ? g_Kb : g_AB;
}

__device__ __forceinline__ void cpasync16(uint32_t saddr, const void* g) {
    asm volatile("cp.async.cg.shared.global [%0], [%1], 16;\n" :: "r"(saddr), "l"(g));
}

// -------- fused: sigmoid(adjacency) + build Wc[96][128] = [var_emb; temp_emb; 0] --------
__global__ void prelude_kernel(const float* __restrict__ logits,
                               const float* __restrict__ var_emb,
                               const float* __restrict__ temp_emb) {
    int idx = blockIdx.x * 256 + threadIdx.x;
    if (idx < VV*VV*LLP1) {
        float v = logits[idx];
        g_adj[idx] = 1.f / (1.f + expf(-v));
    }
    int idx2 = idx - VV*VV*LLP1;
    if (idx2 >= 0 && idx2 < KAB*HH) {
        int r = idx2 >> 7, h = idx2 & 127;
        float val = 0.f;
        if (r < VV) val = var_emb[r*HH + h];
        else if (r < VV + LLP1) val = temp_emb[(r - VV)*HH + h];
        g_Wc[idx2] = val;
    }
}

// -------- fold O-proj into output head: weff[v]=Wo[v]@outW[v], beff[v]=bo.outW+outb --------
__global__ void build_weff_kernel(const float* __restrict__ Wo,
                                  const float* __restrict__ bo,
                                  const float* __restrict__ outW,
                                  const float* __restrict__ outb) {
    const int v = blockIdx.x;
    const int h = threadIdx.x;   // 128
    __shared__ float sw[HH];
    __shared__ float red[HH];
    sw[h] = outW[v*HH + h];
    __syncthreads();
    const float* wp = Wo + ((size_t)v*HH + h)*HH;
    float s = 0.f;
    #pragma unroll 8
    for (int k = 0; k < HH; k++) s = fmaf(wp[k], sw[k], s);
    g_weff[v*HH + h] = s;
    red[h] = bo[v*HH + h] * sw[h];
    __syncthreads();
    #pragma unroll
    for (int o = 64; o > 0; o >>= 1) {
        if (h < o) red[h] += red[h + o];
        __syncthreads();
    }
    if (h == 0) g_beff[v] = red[0] + outb[v];
}

// -------- fold V-proj through the head; grid (V, 4), one output per thread --------
__global__ void build_Wvy_kernel(const float* __restrict__ Wv,
                                 const float* __restrict__ bv) {
    const int v = blockIdx.x;
    const int q = blockIdx.y;
    const int t = threadIdx.x;   // 256
    __shared__ float wsh[HH];
    if (t < HH) wsh[t] = g_weff[v*HH + t];
    __syncthreads();
    const int e = q*256 + t;     // e = h*8 + n
    const int h = e >> 3, n = e & 7;
    const float* wp = Wv + ((size_t)v*HH + h)*HH + n*DHH;
    const float* gp = wsh + n*DHH;
    float4 x0 = *(const float4*)(wp),   x1 = *(const float4*)(wp+4);
    float4 x2 = *(const float4*)(wp+8), x3 = *(const float4*)(wp+12);
    float4 g0 = *(const float4*)(gp),   g1 = *(const float4*)(gp+4);
    float4 g2 = *(const float4*)(gp+8), g3 = *(const float4*)(gp+12);
    float s0 = x0.x*g0.x + x0.y*g0.y + x0.z*g0.z + x0.w*g0.w;
    float s1 = x1.x*g1.x + x1.y*g1.y + x1.z*g1.z + x1.w*g1.w;
    float s2 = x2.x*g2.x + x2.y*g2.y + x2.z*g2.z + x2.w*g2.w;
    float s3 = x3.x*g3.x + x3.y*g3.y + x3.z*g3.z + x3.w*g3.w;
    g_Wvy[(size_t)v*HH*NHH + e] = (s0 + s1) + (s2 + s3);
    if (q == 0 && t < NHH) {
        const float* bp = bv + (size_t)v*HH + t*DHH;
        const float* gp2 = wsh + t*DHH;
        float s = 0.f;
        #pragma unroll
        for (int d = 0; d < DHH; d++) s = fmaf(bp[d], gp2[d], s);
        g_cy[v*NHH + t] = s;
    }
}

// -------- stage AB_T[i][k][m]; 256 threads: s-range split in half --------
__global__ void __launch_bounds__(256) build_AB_kernel(const float* __restrict__ x) {
    const int i  = blockIdx.x;
    const int b  = blockIdx.y;
    const int t0 = blockIdx.z * 128;
    __shared__ float xsh[VV][140];
    __shared__ float adjs[VV][12];
    __shared__ float blsh[LLP1][129];
    const int tid = threadIdx.x;     // 256

    for (int f = tid; f < 138*16; f += 256) {
        int j = f >> 4, s4 = f & 15;
        int t = t0 - 10 + j;
        float4 xv = make_float4(0.f, 0.f, 0.f, 0.f);
        if (t >= 0) xv = *(const float4*)(x + ((size_t)(b*SS + t))*VV + s4*4);
        xsh[s4*4+0][j] = xv.x;
        xsh[s4*4+1][j] = xv.y;
        xsh[s4*4+2][j] = xv.z;
        xsh[s4*4+3][j] = xv.w;
    }
    for (int f = tid; f < VV*LLP1; f += 256) {
        int s = f / LLP1, l = f - s*LLP1;
        adjs[s][l] = g_adj[((size_t)s*VV + i)*LLP1 + l];
    }
    __syncthreads();

    const int t    = tid & 127;
    const int half = tid >> 7;
    const int j0 = t + 10;
    float bl[LLP1];
    #pragma unroll
    for (int l = 0; l < LLP1; l++) bl[l] = 0.f;

    float* ABi = g_AB + (size_t)i*KAB*MM + b*SS + t0;
    const int s0 = half*32;
    #pragma unroll 2
    for (int s = s0; s < s0 + 32; s++) {
        const float* xr = xsh[s];
        const float* ar = adjs[s];
        float a = 0.f;
        #pragma unroll
        for (int l = 0; l < LLP1; l++) {
            float p = xr[j0 - l] * ar[l];
            a += p;
            bl[l] += p;
        }
        ABi[(size_t)s*MM + t] = a;
    }
    if (half == 1) {
        #pragma unroll
        for (int l = 0; l < LLP1; l++) blsh[l][t] = bl[l];
    }
    __syncthreads();
    if (half == 0) {
        #pragma unroll
        for (int l = 0; l < LLP1; l++) ABi[(size_t)(VV + l)*MM + t] = bl[l] + blsh[l][t];
    } else {
        #pragma unroll
        for (int r = VV + LLP1; r < KAB; r++) ABi[(size_t)r*MM + t] = 0.f;
    }
}

// -------- batched per-variable GEMM (64x128 tile, KT=32, double-buffered) --------
// MODE 0: bias + LayerNorm + exact GELU   MODE 1: bias   MODE 2: plain
// DUAL: blockIdx.z==1 uses (Wall2, ball2, dst2)
template<int MODE, int KDIM, bool XT, bool SHW, bool DUAL>
__global__ void __launch_bounds__(256, 2)
gemm2(int src, int dst,
      const float* __restrict__ Wall, const float* __restrict__ ball,
      const float* __restrict__ lng, const float* __restrict__ lnb, int li,
      const float* __restrict__ Wall2, const float* __restrict__ ball2, int dst2)
{
    constexpr int NK = KDIM / 32;
    __shared__ float As[2][32][64];   // 16 KB
    __shared__ float Bs[2][32][128];  // 32 KB  (total 48 KB)
    const uint32_t As_u = (uint32_t)__cvta_generic_to_shared(&As[0][0][0]);
    const uint32_t Bs_u = (uint32_t)__cvta_generic_to_shared(&Bs[0][0][0]);

    const float* WallX = Wall;
    const float* ballX = ball;
    int dstX = dst;
    if (DUAL && blockIdx.z == 1) { WallX = Wall2; ballX = ball2; dstX = dst2; }

    const int v   = blockIdx.y;
    const int m0  = blockIdx.x * 64;
    const int tid = threadIdx.x;
    const int w = tid >> 5, lane = tid & 31;

    const float* Xb = buf_sel(src);
    const float* Xv = XT ? (Xb + (size_t)v*KDIM*MM)
                         : (Xb + ((size_t)v*MM + m0)*KDIM);
    const float* Wv = SHW ? g_Wc
                    : (MODE == 0 ? WallX + ((size_t)v*NLL + li)*HH*HH
                                 : WallX + (size_t)v*HH*HH);

    float acc[8][4];
    #pragma unroll
    for (int r = 0; r < 8; r++) { acc[r][0]=0.f; acc[r][1]=0.f; acc[r][2]=0.f; acc[r][3]=0.f; }

    const int am = tid >> 2, ak = tid & 3;
    const int xkr = tid >> 3, xms = tid & 7;
    float4 pa0, pa1;

    auto issueA = [&](int k0, int buf) {
        if (XT) {
            const float* g = Xv + (size_t)(k0 + xkr)*MM + m0 + xms*8;
            uint32_t d = As_u + (uint32_t)((buf*2048 + xkr*64 + xms*8) * 4);
            cpasync16(d, g);
            cpasync16(d + 16, g + 4);
        } else {
            const float* g = Xv + (size_t)am*KDIM + k0 + ak*8;
            pa0 = *(const float4*)g;
            pa1 = *(const float4*)(g + 4);
        }
    };
    auto storeA = [&](int buf) {
        if (!XT) {
            float* base = &As[buf][0][0] + am;
            base[(ak*8+0)*64] = pa0.x; base[(ak*8+1)*64] = pa0.y;
            base[(ak*8+2)*64] = pa0.z; base[(ak*8+3)*64] = pa0.w;
            base[(ak*8+4)*64] = pa1.x; base[(ak*8+5)*64] = pa1.y;
            base[(ak*8+6)*64] = pa1.z; base[(ak*8+7)*64] = pa1.w;
        }
    };
    auto issueB = [&](int k0, int buf) {
        #pragma unroll
        for (int i2 = 0; i2 < 4; i2++) {
            int s = tid + i2*256;
            int kr = s >> 5, c4 = (s & 31) << 2;
            uint32_t d = Bs_u + (uint32_t)((buf*4096 + kr*128 + c4) * 4);
            cpasync16(d, Wv + (size_t)(k0 + kr)*HH + c4);
        }
    };

    issueA(0, 0);
    issueB(0, 0);
    storeA(0);
    asm volatile("cp.async.commit_group;\n");
    asm volatile("cp.async.wait_group 0;\n" ::: "memory");
    __syncthreads();

    #pragma unroll 1
    for (int kt = 0; kt < NK; kt++) {
        const int cur = kt & 1, nxt = cur ^ 1;
        if (kt + 1 < NK) {
            issueA((kt + 1)*32, nxt);
            issueB((kt + 1)*32, nxt);
            asm volatile("cp.async.commit_group;\n");
        }
        const float* Ap = &As[cur][0][0] + w*8;
        const float* Bp = &Bs[cur][0][0] + (lane << 2);
        #pragma unroll 8
        for (int kk = 0; kk < 32; kk++) {
            float4 a0 = *(const float4*)(Ap + kk*64);
            float4 a1 = *(const float4*)(Ap + kk*64 + 4);
            float4 b  = *(const float4*)(Bp + kk*128);
            float ar[8] = {a0.x,a0.y,a0.z,a0.w,a1.x,a1.y,a1.z,a1.w};
            #pragma unroll
            for (int r = 0; r < 8; r++) {
                acc[r][0] = fmaf(ar[r], b.x, acc[r][0]);
                acc[r][1] = fmaf(ar[r], b.y, acc[r][1]);
                acc[r][2] = fmaf(ar[r], b.z, acc[r][2]);
                acc[r][3] = fmaf(ar[r], b.w, acc[r][3]);
            }
        }
        if (kt + 1 < NK) {
            storeA(nxt);
            asm volatile("cp.async.wait_group 0;\n" ::: "memory");
            __syncthreads();
        }
    }

    if (MODE < 2) {
        const float* bvp = (MODE == 0) ? ballX + ((size_t)v*NLL + li)*HH
                                       : ballX + (size_t)v*HH;
        float4 bias = *(const float4*)(bvp + lane*4);
        #pragma unroll
        for (int r = 0; r < 8; r++) {
            acc[r][0] += bias.x; acc[r][1] += bias.y;
            acc[r][2] += bias.z; acc[r][3] += bias.w;
        }
    }

    if (MODE == 0) {
        const float* gp = lng + ((size_t)v*NLL + li)*HH;
        const float* bp = lnb + ((size_t)v*NLL + li)*HH;
        float4 gv4 = *(const float4*)(gp + lane*4);
        float4 bv4 = *(const float4*)(bp + lane*4);
        float gg[4] = {gv4.x, gv4.y, gv4.z, gv4.w};
        float bt[4] = {bv4.x, bv4.y, bv4.z, bv4.w};
        #pragma unroll
        for (int r = 0; r < 8; r++) {
            float s1 = acc[r][0] + acc[r][1] + acc[r][2] + acc[r][3];
            float s2 = acc[r][0]*acc[r][0] + acc[r][1]*acc[r][1]
                     + acc[r][2]*acc[r][2] + acc[r][3]*acc[r][3];
            #pragma unroll
            for (int o = 16; o > 0; o >>= 1) {
                s1 += __shfl_xor_sync(0xffffffffu, s1, o);
                s2 += __shfl_xor_sync(0xffffffffu, s2, o);
            }
            float mu  = s1 * (1.f/128.f);
            float var = s2 * (1.f/128.f) - mu*mu;
            float inv = rsqrtf(var + 1e-5f);
            #pragma unroll
            for (int c = 0; c < 4; c++) {
                float xx = (acc[r][c] - mu) * inv * gg[c] + bt[c];
                acc[r][c] = 0.5f * xx * (1.f + erff(xx * 0.70710678118654752f));
            }
        }
    }

    float* Yv = buf_sel(dstX) + ((size_t)v*MM + m0)*HH;
    #pragma unroll
    for (int r = 0; r < 8; r++) {
        float4 st = make_float4(acc[r][0], acc[r][1], acc[r][2], acc[r][3]);
        *(float4*)(Yv + (size_t)(w*8 + r)*HH + lane*4) = st;
    }
}

// -------- y8: Y8[n][v][m] = Z2[v,m,:].Wvy[v,:,n] + cy[v,n] --------
__global__ void __launch_bounds__(256) y8_kernel() {
    const int v = blockIdx.x, b = blockIdx.y;
    __shared__ __align__(16) float wv_sh[HH][NHH];   // 4 KB
    const int t = threadIdx.x;
    {
        const float4* src = (const float4*)(g_Wvy + (size_t)v*HH*NHH);
        float4* dst = (float4*)&wv_sh[0][0];
        dst[t] = src[t];
    }
    __syncthreads();

    const float* zr = g_Z2 + ((size_t)v*MM + (size_t)b*SS + t)*HH;
    float ya[NHH];
    #pragma unroll
    for (int n = 0; n < NHH; n++) ya[n] = g_cy[v*NHH + n];
    #pragma unroll 4
    for (int h0 = 0; h0 < HH; h0 += 4) {
        float4 z = *(const float4*)(zr + h0);
        const float zz[4] = {z.x, z.y, z.z, z.w};
        #pragma unroll
        for (int hi = 0; hi < 4; hi++) {
            float4 w0 = *(const float4*)&wv_sh[h0 + hi][0];
            float4 w1 = *(const float4*)&wv_sh[h0 + hi][4];
            ya[0] = fmaf(zz[hi], w0.x, ya[0]);
            ya[1] = fmaf(zz[hi], w0.y, ya[1]);
            ya[2] = fmaf(zz[hi], w0.z, ya[2]);
            ya[3] = fmaf(zz[hi], w0.w, ya[3]);
            ya[4] = fmaf(zz[hi], w1.x, ya[4]);
            ya[5] = fmaf(zz[hi], w1.y, ya[5]);
            ya[6] = fmaf(zz[hi], w1.z, ya[6]);
            ya[7] = fmaf(zz[hi], w1.w, ya[7]);
        }
    }
    const size_t mo = (size_t)v*MM + (size_t)b*SS + t;
    #pragma unroll
    for (int n = 0; n < NHH; n++) g_Y8[(size_t)n*VV*MM + mo] = ya[n];
}

// -------- attention: 128 threads, 2 queries/thread, raw-exp softmax --------
__global__ void __launch_bounds__(128) attn4_kernel() {
    const int n = blockIdx.x, v = blockIdx.y, b = blockIdx.z;
    __shared__ __align__(16) float Ks[SS][DHH];   // 16 KB
    __shared__ __align__(8)  float ys[SS];        // 1 KB

    const int t = threadIdx.x;   // 0..127; owns queries t and t+128
    const size_t base = ((size_t)v*MM + (size_t)b*SS)*HH + n*DHH;
    const size_t mo0 = (size_t)v*MM + (size_t)b*SS;

    #pragma unroll
    for (int r0 = 0; r0 < 2; r0++) {
        const int r = t + r0*128;
        const float* Kp = g_Kb + base + (size_t)r*HH;
        *(float4*)&Ks[r][0]  = *(const float4*)(Kp);
        *(float4*)&Ks[r][4]  = *(const float4*)(Kp + 4);
        *(float4*)&Ks[r][8]  = *(const float4*)(Kp + 8);
        *(float4*)&Ks[r][12] = *(const float4*)(Kp + 12);
        ys[r] = g_Y8[(size_t)n*VV*MM + mo0 + r];
    }

    const float sc = 0.25f;   // 1/sqrt(DH)
    float4 qa0, qa1, qa2, qa3, qb0, qb1, qb2, qb3;
    {
        const float* Qp = g_Qb + base + (size_t)t*HH;
        qa0 = *(const float4*)(Qp);     qa1 = *(const float4*)(Qp + 4);
        qa2 = *(const float4*)(Qp + 8); qa3 = *(const float4*)(Qp + 12);
        const float* Qp2 = g_Qb + base + (size_t)(t + 128)*HH;
        qb0 = *(const float4*)(Qp2);     qb1 = *(const float4*)(Qp2 + 4);
        qb2 = *(const float4*)(Qp2 + 8); qb3 = *(const float4*)(Qp2 + 12);
    }
    qa0.x*=sc; qa0.y*=sc; qa0.z*=sc; qa0.w*=sc;
    qa1.x*=sc; qa1.y*=sc; qa1.z*=sc; qa1.w*=sc;
    qa2.x*=sc; qa2.y*=sc; qa2.z*=sc; qa2.w*=sc;
    qa3.x*=sc; qa3.y*=sc; qa3.z*=sc; qa3.w*=sc;
    qb0.x*=sc; qb0.y*=sc; qb0.z*=sc; qb0.w*=sc;
    qb1.x*=sc; qb1.y*=sc; qb1.z*=sc; qb1.w*=sc;
    qb2.x*=sc; qb2.y*=sc; qb2.z*=sc; qb2.w*=sc;
    qb3.x*=sc; qb3.y*=sc; qb3.z*=sc; qb3.w*=sc;
    __syncthreads();

    float la = 0.f, lb = 0.f, aa = 0.f, ab = 0.f;

    #pragma unroll 2
    for (int j = 0; j < SS; j += 2) {
        const float4* kr0 = (const float4*)Ks[j];
        const float4* kr1 = (const float4*)Ks[j+1];
        float4 k00=kr0[0], k01=kr0[1], k02=kr0[2], k03=kr0[3];
        float4 k10=kr1[0], k11=kr1[1], k12=kr1[2], k13=kr1[3];

        float sa0 = ((qa0.x*k00.x + qa0.y*k00.y) + (qa0.z*k00.z + qa0.w*k00.w))
                  + ((qa1.x*k01.x + qa1.y*k01.y) + (qa1.z*k01.z + qa1.w*k01.w))
                  + ((qa2.x*k02.x + qa2.y*k02.y) + (qa2.z*k02.z + qa2.w*k02.w))
                  + ((qa3.x*k03.x + qa3.y*k03.y) + (qa3.z*k03.z + qa3.w*k03.w));
        float sb0 = ((qb0.x*k00.x + qb0.y*k00.y) + (qb0.z*k00.z + qb0.w*k00.w))
                  + ((qb1.x*k01.x + qb1.y*k01.y) + (qb1.z*k01.z + qb1.w*k01.w))
                  + ((qb2.x*k02.x + qb2.y*k02.y) + (qb2.z*k02.z + qb2.w*k02.w))
                  + ((qb3.x*k03.x + qb3.y*k03.y) + (qb3.z*k03.z + qb3.w*k03.w));
        float sa1 = ((qa0.x*k10.x + qa0.y*k10.y) + (qa0.z*k10.z + qa0.w*k10.w))
                  + ((qa1.x*k11.x + qa1.y*k11.y) + (qa1.z*k11.z + qa1.w*k11.w))
                  + ((qa2.x*k12.x + qa2.y*k12.y) + (qa2.z*k12.z + qa2.w*k12.w))
                  + ((qa3.x*k13.x + qa3.y*k13.y) + (qa3.z*k13.z + qa3.w*k13.w));
        float sb1 = ((qb0.x*k10.x + qb0.y*k10.y) + (qb0.z*k10.z + qb0.w*k10.w))
                  + ((qb1.x*k11.x + qb1.y*k11.y) + (qb1.z*k11.z + qb1.w*k11.w))
                  + ((qb2.x*k12.x + qb2.y*k12.y) + (qb2.z*k12.z + qb2.w*k12.w))
                  + ((qb3.x*k13.x + qb3.y*k13.y) + (qb3.z*k13.z + qb3.w*k13.w));

        float ea0 = __expf(sa0), ea1 = __expf(sa1);
        float eb0 = __expf(sb0), eb1 = __expf(sb1);
        float2 y2 = *(const float2*)&ys[j];
        la += ea0 + ea1;
        lb += eb0 + eb1;
        aa = fmaf(ea0, y2.x, fmaf(ea1, y2.y, aa));
        ab = fmaf(eb0, y2.x, fmaf(eb1, y2.y, ab));
    }

    g_P[(size_t)n*VV*MM + mo0 + t]       = aa / la;
    g_P[(size_t)n*VV*MM + mo0 + t + 128] = ab / lb;
}

// -------- reduce heads + beff -> out[m][v] --------
__global__ void reduce_kernel(float* __restrict__ out) {
    const int e = blockIdx.x * 256 + threadIdx.x;   // e = v*MM + m
    if (e >= VV*MM) return;
    const int v = e >> 10;
    const int m = e & 1023;
    float s = g_beff[v];
    #pragma unroll
    for (int n = 0; n < NHH; n++) s += g_P[(size_t)n*VV*MM + e];
    out[(size_t)m*VV + v] = s;
}

extern "C" void kernel_launch(void* const* d_in, const int* in_sizes, int n_in,
                              void* d_out, int out_size) {
    const float* x        = (const float*)d_in[0];
    const float* adjl     = (const float*)d_in[1];
    const float* var_emb  = (const float*)d_in[2];
    const float* temp_emb = (const float*)d_in[3];
    const float* mech_W   = (const float*)d_in[4];
    const float* mech_b   = (const float*)d_in[5];
    const float* ln_g     = (const float*)d_in[6];
    const float* ln_b     = (const float*)d_in[7];
    const float* Wq       = (const float*)d_in[8];
    const float* Wk       = (const float*)d_in[9];
    const float* Wv       = (const float*)d_in[10];
    const float* Wo       = (const float*)d_in[11];
    const float* bq       = (const float*)d_in[12];
    const float* bk       = (const float*)d_in[13];
    const float* bv       = (const float*)d_in[14];
    const float* bo       = (const float*)d_in[15];
    const float* out_W    = (const float*)d_in[16];
    const float* out_b    = (const float*)d_in[17];
    float* out = (float*)d_out;

    prelude_kernel<<<(VV*VV*LLP1 + KAB*HH + 255)/256, 256>>>(adjl, var_emb, temp_emb);
    build_weff_kernel<<<VV, 128>>>(Wo, bo, out_W, out_b);
    build_Wvy_kernel<<<dim3(VV, 4), 256>>>(Wv, bv);
    build_AB_kernel<<<dim3(VV, BB, 2), 256>>>(x);

    // causal z = AB @ Wc  -> Z1
    gemm2<2,KAB,true,true,false><<<dim3(16, VV), 256>>>(4, 0, nullptr, nullptr, nullptr, nullptr, 0,
                                                        nullptr, nullptr, 0);

    // mech layers: Z1 -> Z2 -> Z1 -> Z2
    gemm2<0,128,false,false,false><<<dim3(16, VV), 256>>>(0, 1, mech_W, mech_b, ln_g, ln_b, 0,
                                                          nullptr, nullptr, 0);
    gemm2<0,128,false,false,false><<<dim3(16, VV), 256>>>(1, 0, mech_W, mech_b, ln_g, ln_b, 1,
                                                          nullptr, nullptr, 0);
    gemm2<0,128,false,false,false><<<dim3(16, VV), 256>>>(0, 1, mech_W, mech_b, ln_g, ln_b, 2,
                                                          nullptr, nullptr, 0);

    // folded V path: Y8 = Z2 @ Wvy + cy
    y8_kernel<<<dim3(VV, BB), 256>>>();

    // Q and K projections from Z2 in ONE launch (z=0 -> Qb, z=1 -> Kb)
    gemm2<1,128,false,false,true><<<dim3(16, VV, 2), 256>>>(1, 2, Wq, bq, nullptr, nullptr, 0,
                                                            Wk, bk, 3);

    // attention partials per head (2 queries/thread)
    attn4_kernel<<<dim3(NHH, VV, BB), 128>>>();

    // sum heads + bias -> out
    reduce_kernel<<<(VV*MM + 255)/256, 256>>>(out);
}

// round 13
// speedup vs baseline: 1.3966x; 1.2426x over previous
#include <cuda_runtime.h>
#include <cuda_bf16.h>
#include <math.h>
#include <stdint.h>

#define BB  4
#define SS  256
#define VV  64
#define HH  128
#define NHH 8
#define DHH 16
#define NLL 3
#define LLP1 11
#define MM  (BB*SS)   // 1024
#define KAB 96        // padded causal K (64 A + 11 Bl + 21 zero)

// weight-tile arena: tiles of [128 n][16 kperm] bf16 (2048 bf16 = 256 uint4 each)
// mech: tiles 0..1535 (vli*8+kb), Wq: 1536.., Wk: 2048.., Wc: 2560..2565
#define T_Q  1536
#define T_K  2048
#define T_WC 2560
#define NTILES 2566

// -------- device scratch (static; allocation-free) --------
__device__ float g_adj[VV*VV*LLP1];
__device__ float g_Z1[(size_t)VV*MM*HH];
__device__ float g_Z2[(size_t)VV*MM*HH];
__device__ float g_Qb[(size_t)VV*MM*HH];
__device__ float g_Kb[(size_t)VV*MM*HH];
__device__ float g_AB[(size_t)VV*KAB*MM];   // k-major: [v][k][m]
__device__ float g_Wc[KAB*HH];
__device__ float g_weff[VV*HH];
__device__ float g_beff[VV];
__device__ float g_Wvy[(size_t)VV*HH*NHH];  // [v][h*8+n]
__device__ float g_cy[VV*NHH];
__device__ float g_Y8[(size_t)NHH*VV*MM];   // [n][v][m]
__device__ float g_P[(size_t)NHH*VV*MM];    // per-head partials [n][v][m]
__device__ __nv_bfloat16 g_Whi[(size_t)NTILES*2048];
__device__ __nv_bfloat16 g_Wlo[(size_t)NTILES*2048];

__device__ __forceinline__ float* buf_sel(int s) {
    return (s == 0) ? g_Z1 : (s == 1) ? g_Z2 : (s == 2) ? g_Qb
         : (s == 3) ? g_Kb : g_AB;
}

__device__ __forceinline__ void cpasync16(uint32_t saddr, const void* g) {
    asm volatile("cp.async.cg.shared.global [%0], [%1], 16;\n" :: "r"(saddr), "l"(g));
}

// pack two fp32 -> bf16x2 (x0 in low half = lower-k element)
__device__ __forceinline__ uint32_t cvt_pack(float x0, float x1) {
    uint32_t r;
    asm("cvt.rn.bf16x2.f32 %0, %1, %2;" : "=r"(r) : "f"(x1), "f"(x0));
    return r;
}
// hi/lo split of a pair
__device__ __forceinline__ void split_pair(float x0, float x1, uint32_t& h, uint32_t& l) {
    h = cvt_pack(x0, x1);
    float h0 = __uint_as_float(h << 16);
    float h1 = __uint_as_float(h & 0xffff0000u);
    l = cvt_pack(x0 - h0, x1 - h1);
}

__device__ __forceinline__ void mma_bf16(float* d, const uint32_t* a, uint32_t b0, uint32_t b1) {
    asm volatile("mma.sync.aligned.m16n8k16.row.col.f32.bf16.bf16.f32 "
        "{%0,%1,%2,%3}, {%4,%5,%6,%7}, {%8,%9}, {%0,%1,%2,%3};"
        : "+f"(d[0]), "+f"(d[1]), "+f"(d[2]), "+f"(d[3])
        : "r"(a[0]), "r"(a[1]), "r"(a[2]), "r"(a[3]), "r"(b0), "r"(b1));
}

// k-permutation: perm[4*tig+j] = 2tig + (j&1) + (j>=2)*8
__device__ __forceinline__ int kperm(int p) {
    return 2*(p >> 2) + (p & 1) + ((p >> 1) & 1)*8;
}
// inverse: position of k within the 16-block
__device__ __forceinline__ int kinv(int k) {
    return (((k & 7) >> 1) << 2) + (k & 1) + ((k >> 3) << 1);
}

// -------- fused: sigmoid(adjacency) + build Wc[96][128] --------
__global__ void prelude_kernel(const float* __restrict__ logits,
                               const float* __restrict__ var_emb,
                               const float* __restrict__ temp_emb) {
    int idx = blockIdx.x * 256 + threadIdx.x;
    if (idx < VV*VV*LLP1) {
        float v = logits[idx];
        g_adj[idx] = 1.f / (1.f + expf(-v));
    }
    int idx2 = idx - VV*VV*LLP1;
    if (idx2 >= 0 && idx2 < KAB*HH) {
        int r = idx2 >> 7, h = idx2 & 127;
        float val = 0.f;
        if (r < VV) val = var_emb[r*HH + h];
        else if (r < VV + LLP1) val = temp_emb[(r - VV)*HH + h];
        g_Wc[idx2] = val;
    }
}

// -------- split all weights into bf16 hi/lo arena with k-permutation --------
// one block per 16x128 tile
__global__ void __launch_bounds__(256) split_w_kernel(const float* __restrict__ mech_W,
                                                      const float* __restrict__ Wq,
                                                      const float* __restrict__ Wk) {
    const int t = blockIdx.x;
    const int tid = threadIdx.x;
    const float* src;
    if (t < T_Q)       src = mech_W + (size_t)(t >> 3)*16384 + (size_t)(t & 7)*2048;
    else if (t < T_K)  src = Wq + (size_t)((t - T_Q) >> 3)*16384 + (size_t)(t & 7)*2048;
    else if (t < T_WC) src = Wk + (size_t)((t - T_K) >> 3)*16384 + (size_t)(t & 7)*2048;
    else               src = g_Wc + (size_t)(t - T_WC)*2048;

    __shared__ float ws[16][129];
    {
        int e = tid*8;
        int r = e >> 7, c = e & 127;
        float4 a = *(const float4*)(src + e);
        float4 b = *(const float4*)(src + e + 4);
        ws[r][c+0]=a.x; ws[r][c+1]=a.y; ws[r][c+2]=a.z; ws[r][c+3]=a.w;
        ws[r][c+4]=b.x; ws[r][c+5]=b.y; ws[r][c+6]=b.z; ws[r][c+7]=b.w;
    }
    __syncthreads();

    const int n  = tid >> 1;
    const int p0 = (tid & 1)*8;
    uint32_t hw[4], lw[4];
    #pragma unroll
    for (int jp = 0; jp < 4; jp++) {
        float x0 = ws[kperm(p0 + jp*2 + 0)][n];
        float x1 = ws[kperm(p0 + jp*2 + 1)][n];
        split_pair(x0, x1, hw[jp], lw[jp]);
    }
    // tile = 2048 bf16 = 256 uint4; bf16 offset within tile = n*16 + p0 = tid*8
    ((uint4*)g_Whi)[(size_t)t*256 + tid] = make_uint4(hw[0], hw[1], hw[2], hw[3]);
    ((uint4*)g_Wlo)[(size_t)t*256 + tid] = make_uint4(lw[0], lw[1], lw[2], lw[3]);
}

// -------- fold O-proj into output head --------
__global__ void build_weff_kernel(const float* __restrict__ Wo,
                                  const float* __restrict__ bo,
                                  const float* __restrict__ outW,
                                  const float* __restrict__ outb) {
    const int v = blockIdx.x;
    const int h = threadIdx.x;   // 128
    __shared__ float sw[HH];
    __shared__ float red[HH];
    sw[h] = outW[v*HH + h];
    __syncthreads();
    const float* wp = Wo + ((size_t)v*HH + h)*HH;
    float s = 0.f;
    #pragma unroll 8
    for (int k = 0; k < HH; k++) s = fmaf(wp[k], sw[k], s);
    g_weff[v*HH + h] = s;
    red[h] = bo[v*HH + h] * sw[h];
    __syncthreads();
    #pragma unroll
    for (int o = 64; o > 0; o >>= 1) {
        if (h < o) red[h] += red[h + o];
        __syncthreads();
    }
    if (h == 0) g_beff[v] = red[0] + outb[v];
}

// -------- fold V-proj through the head --------
__global__ void build_Wvy_kernel(const float* __restrict__ Wv,
                                 const float* __restrict__ bv) {
    const int v = blockIdx.x;
    const int q = blockIdx.y;
    const int t = threadIdx.x;   // 256
    __shared__ float wsh[HH];
    if (t < HH) wsh[t] = g_weff[v*HH + t];
    __syncthreads();
    const int e = q*256 + t;     // e = h*8 + n
    const int h = e >> 3, n = e & 7;
    const float* wp = Wv + ((size_t)v*HH + h)*HH + n*DHH;
    const float* gp = wsh + n*DHH;
    float4 x0 = *(const float4*)(wp),   x1 = *(const float4*)(wp+4);
    float4 x2 = *(const float4*)(wp+8), x3 = *(const float4*)(wp+12);
    float4 g0 = *(const float4*)(gp),   g1 = *(const float4*)(gp+4);
    float4 g2 = *(const float4*)(gp+8), g3 = *(const float4*)(gp+12);
    float s0 = x0.x*g0.x + x0.y*g0.y + x0.z*g0.z + x0.w*g0.w;
    float s1 = x1.x*g1.x + x1.y*g1.y + x1.z*g1.z + x1.w*g1.w;
    float s2 = x2.x*g2.x + x2.y*g2.y + x2.z*g2.z + x2.w*g2.w;
    float s3 = x3.x*g3.x + x3.y*g3.y + x3.z*g3.z + x3.w*g3.w;
    g_Wvy[(size_t)v*HH*NHH + e] = (s0 + s1) + (s2 + s3);
    if (q == 0 && t < NHH) {
        const float* bp = bv + (size_t)v*HH + t*DHH;
        const float* gp2 = wsh + t*DHH;
        float s = 0.f;
        #pragma unroll
        for (int d = 0; d < DHH; d++) s = fmaf(bp[d], gp2[d], s);
        g_cy[v*NHH + t] = s;
    }
}

// -------- stage AB_T[i][k][m] --------
__global__ void __launch_bounds__(256) build_AB_kernel(const float* __restrict__ x) {
    const int i  = blockIdx.x;
    const int b  = blockIdx.y;
    const int t0 = blockIdx.z * 128;
    __shared__ float xsh[VV][140];
    __shared__ float adjs[VV][12];
    __shared__ float blsh[LLP1][129];
    const int tid = threadIdx.x;     // 256

    for (int f = tid; f < 138*16; f += 256) {
        int j = f >> 4, s4 = f & 15;
        int t = t0 - 10 + j;
        float4 xv = make_float4(0.f, 0.f, 0.f, 0.f);
        if (t >= 0) xv = *(const float4*)(x + ((size_t)(b*SS + t))*VV + s4*4);
        xsh[s4*4+0][j] = xv.x;
        xsh[s4*4+1][j] = xv.y;
        xsh[s4*4+2][j] = xv.z;
        xsh[s4*4+3][j] = xv.w;
    }
    for (int f = tid; f < VV*LLP1; f += 256) {
        int s = f / LLP1, l = f - s*LLP1;
        adjs[s][l] = g_adj[((size_t)s*VV + i)*LLP1 + l];
    }
    __syncthreads();

    const int t    = tid & 127;
    const int half = tid >> 7;
    const int j0 = t + 10;
    float bl[LLP1];
    #pragma unroll
    for (int l = 0; l < LLP1; l++) bl[l] = 0.f;

    float* ABi = g_AB + (size_t)i*KAB*MM + b*SS + t0;
    const int s0 = half*32;
    #pragma unroll 2
    for (int s = s0; s < s0 + 32; s++) {
        const float* xr = xsh[s];
        const float* ar = adjs[s];
        float a = 0.f;
        #pragma unroll
        for (int l = 0; l < LLP1; l++) {
            float p = xr[j0 - l] * ar[l];
            a += p;
            bl[l] += p;
        }
        ABi[(size_t)s*MM + t] = a;
    }
    if (half == 1) {
        #pragma unroll
        for (int l = 0; l < LLP1; l++) blsh[l][t] = bl[l];
    }
    __syncthreads();
    if (half == 0) {
        #pragma unroll
        for (int l = 0; l < LLP1; l++) ABi[(size_t)(VV + l)*MM + t] = bl[l] + blsh[l][t];
    } else {
        #pragma unroll
        for (int r = VV + LLP1; r < KAB; r++) ABi[(size_t)r*MM + t] = 0.f;
    }
}

// -------- tensor-core GEMM: 128x128 tile, KT=16, bf16-split x3 --------
// MODE 0: bias + LayerNorm + GELU   MODE 1: bias   MODE 2: plain
// XT: activations k-major [v][k][m]   DUAL: blockIdx.z picks (tb2,ball2,dst2)
template<int MODE, int KDIM, bool XT, bool DUAL>
__global__ void __launch_bounds__(256, 2)
gemm4(int src, int dst, int tbase, int tstride,
      const float* __restrict__ ball,
      const float* __restrict__ lng, const float* __restrict__ lnb, int li,
      int tbase2, const float* __restrict__ ball2, int dst2)
{
    constexpr int NK = KDIM / 16;
    __shared__ float As[2][16][160];                 // 20.5 KB (padded: conflict-free frags)
    __shared__ __nv_bfloat16 Bh[2][128][16];         // 8 KB
    __shared__ __nv_bfloat16 Bl[2][128][16];         // 8 KB
    __shared__ float sBias[128], sG[128], sBt[128];
    const uint32_t As_u = (uint32_t)__cvta_generic_to_shared(&As[0][0][0]);
    const uint32_t Bh_u = (uint32_t)__cvta_generic_to_shared(&Bh[0][0][0]);
    const uint32_t Bl_u = (uint32_t)__cvta_generic_to_shared(&Bl[0][0][0]);

    const int v   = blockIdx.y;
    const int m0  = blockIdx.x * 128;
    const int tid = threadIdx.x;
    const int w = tid >> 5, lane = tid & 31;
    const int g = lane >> 2, tig = lane & 3;

    const float* ballX = ball;
    int dstX = dst, tbX = tbase;
    if (DUAL && blockIdx.z == 1) { ballX = ball2; dstX = dst2; tbX = tbase2; }
    const int tb = tbX + v*tstride;

    const float* Xb = buf_sel(src);
    const float* Xv = XT ? (Xb + (size_t)v*KDIM*MM)
                         : (Xb + ((size_t)v*MM + m0)*HH);

    // epilogue param preload
    if (MODE < 2 && tid < 128)
        sBias[tid] = (MODE == 0) ? ballX[((size_t)v*NLL + li)*HH + tid]
                                 : ballX[(size_t)v*HH + tid];
    if (MODE == 0 && tid < 128) {
        sG[tid]  = lng[((size_t)v*NLL + li)*HH + tid];
        sBt[tid] = lnb[((size_t)v*NLL + li)*HH + tid];
    }

    float d[16][4];
    #pragma unroll
    for (int f = 0; f < 16; f++) { d[f][0]=0.f; d[f][1]=0.f; d[f][2]=0.f; d[f][3]=0.f; }

    float4 pa0, pa1;
    const int am = tid >> 1, kseg = tid & 1;     // !XT A loader
    const int xr = tid >> 4, xseg = tid & 15;    // XT A loader

    auto issueA = [&](int kt, int buf) {
        if (XT) {
            const float* gp = Xv + (size_t)(kt*16 + xr)*MM + m0 + xseg*8;
            uint32_t dsa = As_u + (uint32_t)((buf*16*160 + kinv(xr)*160 + xseg*8) * 4);
            cpasync16(dsa, gp);
            cpasync16(dsa + 16, gp + 4);
        } else {
            const float* gp = Xv + (size_t)am*HH + kt*16 + kseg*8;
            pa0 = *(const float4*)gp;
            pa1 = *(const float4*)(gp + 4);
        }
    };
    auto storeA = [&](int buf) {
        if (!XT) {
            float* base = &As[buf][0][0] + am;
            const int kb2 = kseg*2;
            base[(0 + kb2)*160] = pa0.x;  base[(1 + kb2)*160]  = pa0.y;
            base[(4 + kb2)*160] = pa0.z;  base[(5 + kb2)*160]  = pa0.w;
            base[(8 + kb2)*160] = pa1.x;  base[(9 + kb2)*160]  = pa1.y;
            base[(12 + kb2)*160] = pa1.z; base[(13 + kb2)*160] = pa1.w;
        }
    };
    auto issueB = [&](int kt, int buf) {
        const char* sh = (const char*)g_Whi + (size_t)(tb + kt)*4096 + tid*16;
        const char* sl = (const char*)g_Wlo + (size_t)(tb + kt)*4096 + tid*16;
        cpasync16(Bh_u + (uint32_t)(buf*4096 + tid*16), sh);
        cpasync16(Bl_u + (uint32_t)(buf*4096 + tid*16), sl);
    };

    issueA(0, 0);
    issueB(0, 0);
    storeA(0);
    asm volatile("cp.async.commit_group;\n");
    asm volatile("cp.async.wait_group 0;\n" ::: "memory");
    __syncthreads();

    const int r0 = w*16 + g;

    #pragma unroll 1
    for (int kt = 0; kt < NK; kt++) {
        const int cur = kt & 1, nxt = cur ^ 1;
        if (kt + 1 < NK) {
            issueA(kt + 1, nxt);
            issueB(kt + 1, nxt);
            asm volatile("cp.async.commit_group;\n");
        }

        float af[8];
        #pragma unroll
        for (int j = 0; j < 4; j++) {
            af[j]     = As[cur][4*tig + j][r0];
            af[4 + j] = As[cur][4*tig + j][r0 + 8];
        }
        uint32_t ah[4], al[4];
        split_pair(af[0], af[1], ah[0], al[0]);   // row g,   k 2tig..+1
        split_pair(af[4], af[5], ah[1], al[1]);   // row g+8, k 2tig..+1
        split_pair(af[2], af[3], ah[2], al[2]);   // row g,   k 2tig+8..+9
        split_pair(af[6], af[7], ah[3], al[3]);   // row g+8, k 2tig+8..+9

        #pragma unroll
        for (int f = 0; f < 16; f++) {
            const int n = f*8 + g;
            uint2 bhv = *(const uint2*)&Bh[cur][n][4*tig];
            uint2 blv = *(const uint2*)&Bl[cur][n][4*tig];
            mma_bf16(d[f], ah, bhv.x, bhv.y);
            mma_bf16(d[f], ah, blv.x, blv.y);
            mma_bf16(d[f], al, bhv.x, bhv.y);
        }

        if (kt + 1 < NK) {
            storeA(nxt);
            asm volatile("cp.async.wait_group 0;\n" ::: "memory");
            __syncthreads();
        }
    }

    if (MODE < 2) {
        #pragma unroll
        for (int f = 0; f < 16; f++) {
            float b0 = sBias[f*8 + 2*tig];
            float b1 = sBias[f*8 + 2*tig + 1];
            d[f][0] += b0; d[f][1] += b1;
            d[f][2] += b0; d[f][3] += b1;
        }
    }

    if (MODE == 0) {
        float s1a = 0.f, s2a = 0.f, s1b = 0.f, s2b = 0.f;
        #pragma unroll
        for (int f = 0; f < 16; f++) {
            s1a += d[f][0] + d[f][1];
            s2a += d[f][0]*d[f][0] + d[f][1]*d[f][1];
            s1b += d[f][2] + d[f][3];
            s2b += d[f][2]*d[f][2] + d[f][3]*d[f][3];
        }
        #pragma unroll
        for (int o = 1; o <= 2; o <<= 1) {
            s1a += __shfl_xor_sync(0xffffffffu, s1a, o);
            s2a += __shfl_xor_sync(0xffffffffu, s2a, o);
            s1b += __shfl_xor_sync(0xffffffffu, s1b, o);
            s2b += __shfl_xor_sync(0xffffffffu, s2b, o);
        }
        float mua  = s1a*(1.f/128.f), mub = s1b*(1.f/128.f);
        float inva = rsqrtf(s2a*(1.f/128.f) - mua*mua + 1e-5f);
        float invb = rsqrtf(s2b*(1.f/128.f) - mub*mub + 1e-5f);
        #pragma unroll
        for (int f = 0; f < 16; f++) {
            const int c0 = f*8 + 2*tig;
            float g0 = sG[c0], g1 = sG[c0+1], t0v = sBt[c0], t1v = sBt[c0+1];
            float x;
            x = (d[f][0] - mua)*inva*g0 + t0v;
            d[f][0] = 0.5f*x*(1.f + erff(x*0.70710678118654752f));
            x = (d[f][1] - mua)*inva*g1 + t1v;
            d[f][1] = 0.5f*x*(1.f + erff(x*0.70710678118654752f));
            x = (d[f][2] - mub)*invb*g0 + t0v;
            d[f][2] = 0.5f*x*(1.f + erff(x*0.70710678118654752f));
            x = (d[f][3] - mub)*invb*g1 + t1v;
            d[f][3] = 0.5f*x*(1.f + erff(x*0.70710678118654752f));
        }
    }

    float* Yv = buf_sel(dstX) + ((size_t)v*MM + m0)*HH;
    #pragma unroll
    for (int f = 0; f < 16; f++) {
        const int c0 = f*8 + 2*tig;
        *(float2*)(Yv + (size_t)r0*HH + c0)       = make_float2(d[f][0], d[f][1]);
        *(float2*)(Yv + (size_t)(r0 + 8)*HH + c0) = make_float2(d[f][2], d[f][3]);
    }
}

// -------- y8: Y8[n][v][m] = Z2[v,m,:].Wvy[v,:,n] + cy[v,n] --------
__global__ void __launch_bounds__(256) y8_kernel() {
    const int v = blockIdx.x, b = blockIdx.y;
    __shared__ __align__(16) float wv_sh[HH][NHH];
    const int t = threadIdx.x;
    {
        const float4* src = (const float4*)(g_Wvy + (size_t)v*HH*NHH);
        float4* dstp = (float4*)&wv_sh[0][0];
        dstp[t] = src[t];
    }
    __syncthreads();

    const float* zr = g_Z2 + ((size_t)v*MM + (size_t)b*SS + t)*HH;
    float ya[NHH];
    #pragma unroll
    for (int n = 0; n < NHH; n++) ya[n] = g_cy[v*NHH + n];
    #pragma unroll 4
    for (int h0 = 0; h0 < HH; h0 += 4) {
        float4 z = *(const float4*)(zr + h0);
        const float zz[4] = {z.x, z.y, z.z, z.w};
        #pragma unroll
        for (int hi = 0; hi < 4; hi++) {
            float4 w0 = *(const float4*)&wv_sh[h0 + hi][0];
            float4 w1 = *(const float4*)&wv_sh[h0 + hi][4];
            ya[0] = fmaf(zz[hi], w0.x, ya[0]);
            ya[1] = fmaf(zz[hi], w0.y, ya[1]);
            ya[2] = fmaf(zz[hi], w0.z, ya[2]);
            ya[3] = fmaf(zz[hi], w0.w, ya[3]);
            ya[4] = fmaf(zz[hi], w1.x, ya[4]);
            ya[5] = fmaf(zz[hi], w1.y, ya[5]);
            ya[6] = fmaf(zz[hi], w1.z, ya[6]);
            ya[7] = fmaf(zz[hi], w1.w, ya[7]);
        }
    }
    const size_t mo = (size_t)v*MM + (size_t)b*SS + t;
    #pragma unroll
    for (int n = 0; n < NHH; n++) g_Y8[(size_t)n*VV*MM + mo] = ya[n];
}

// -------- attention: 128 threads, 2 queries/thread, raw-exp softmax --------
__global__ void __launch_bounds__(128) attn4_kernel() {
    const int n = blockIdx.x, v = blockIdx.y, b = blockIdx.z;
    __shared__ __align__(16) float Ks[SS][DHH];
    __shared__ __align__(8)  float ys[SS];

    const int t = threadIdx.x;
    const size_t base = ((size_t)v*MM + (size_t)b*SS)*HH + n*DHH;
    const size_t mo0 = (size_t)v*MM + (size_t)b*SS;

    #pragma unroll
    for (int r0 = 0; r0 < 2; r0++) {
        const int r = t + r0*128;
        const float* Kp = g_Kb + base + (size_t)r*HH;
        *(float4*)&Ks[r][0]  = *(const float4*)(Kp);
        *(float4*)&Ks[r][4]  = *(const float4*)(Kp + 4);
        *(float4*)&Ks[r][8]  = *(const float4*)(Kp + 8);
        *(float4*)&Ks[r][12] = *(const float4*)(Kp + 12);
        ys[r] = g_Y8[(size_t)n*VV*MM + mo0 + r];
    }

    const float sc = 0.25f;
    float4 qa0, qa1, qa2, qa3, qb0, qb1, qb2, qb3;
    {
        const float* Qp = g_Qb + base + (size_t)t*HH;
        qa0 = *(const float4*)(Qp);     qa1 = *(const float4*)(Qp + 4);
        qa2 = *(const float4*)(Qp + 8); qa3 = *(const float4*)(Qp + 12);
        const float* Qp2 = g_Qb + base + (size_t)(t + 128)*HH;
        qb0 = *(const float4*)(Qp2);     qb1 = *(const float4*)(Qp2 + 4);
        qb2 = *(const float4*)(Qp2 + 8); qb3 = *(const float4*)(Qp2 + 12);
    }
    qa0.x*=sc; qa0.y*=sc; qa0.z*=sc; qa0.w*=sc;
    qa1.x*=sc; qa1.y*=sc; qa1.z*=sc; qa1.w*=sc;
    qa2.x*=sc; qa2.y*=sc; qa2.z*=sc; qa2.w*=sc;
    qa3.x*=sc; qa3.y*=sc; qa3.z*=sc; qa3.w*=sc;
    qb0.x*=sc; qb0.y*=sc; qb0.z*=sc; qb0.w*=sc;
    qb1.x*=sc; qb1.y*=sc; qb1.z*=sc; qb1.w*=sc;
    qb2.x*=sc; qb2.y*=sc; qb2.z*=sc; qb2.w*=sc;
    qb3.x*=sc; qb3.y*=sc; qb3.z*=sc; qb3.w*=sc;
    __syncthreads();

    float la = 0.f, lb = 0.f, aa = 0.f, ab = 0.f;

    #pragma unroll 2
    for (int j = 0; j < SS; j += 2) {
        const float4* kr0 = (const float4*)Ks[j];
        const float4* kr1 = (const float4*)Ks[j+1];
        float4 k00=kr0[0], k01=kr0[1], k02=kr0[2], k03=kr0[3];
        float4 k10=kr1[0], k11=kr1[1], k12=kr1[2], k13=kr1[3];

        float sa0 = ((qa0.x*k00.x + qa0.y*k00.y) + (qa0.z*k00.z + qa0.w*k00.w))
                  + ((qa1.x*k01.x + qa1.y*k01.y) + (qa1.z*k01.z + qa1.w*k01.w))
                  + ((qa2.x*k02.x + qa2.y*k02.y) + (qa2.z*k02.z + qa2.w*k02.w))
                  + ((qa3.x*k03.x + qa3.y*k03.y) + (qa3.z*k03.z + qa3.w*k03.w));
        float sb0 = ((qb0.x*k00.x + qb0.y*k00.y) + (qb0.z*k00.z + qb0.w*k00.w))
                  + ((qb1.x*k01.x + qb1.y*k01.y) + (qb1.z*k01.z + qb1.w*k01.w))
                  + ((qb2.x*k02.x + qb2.y*k02.y) + (qb2.z*k02.z + qb2.w*k02.w))
                  + ((qb3.x*k03.x + qb3.y*k03.y) + (qb3.z*k03.z + qb3.w*k03.w));
        float sa1 = ((qa0.x*k10.x + qa0.y*k10.y) + (qa0.z*k10.z + qa0.w*k10.w))
                  + ((qa1.x*k11.x + qa1.y*k11.y) + (qa1.z*k11.z + qa1.w*k11.w))
                  + ((qa2.x*k12.x + qa2.y*k12.y) + (qa2.z*k12.z + qa2.w*k12.w))
                  + ((qa3.x*k13.x + qa3.y*k13.y) + (qa3.z*k13.z + qa3.w*k13.w));
        float sb1 = ((qb0.x*k10.x + qb0.y*k10.y) + (qb0.z*k10.z + qb0.w*k10.w))
                  + ((qb1.x*k11.x + qb1.y*k11.y) + (qb1.z*k11.z + qb1.w*k11.w))
                  + ((qb2.x*k12.x + qb2.y*k12.y) + (qb2.z*k12.z + qb2.w*k12.w))
                  + ((qb3.x*k13.x + qb3.y*k13.y) + (qb3.z*k13.z + qb3.w*k13.w));

        float ea0 = __expf(sa0), ea1 = __expf(sa1);
        float eb0 = __expf(sb0), eb1 = __expf(sb1);
        float2 y2 = *(const float2*)&ys[j];
        la += ea0 + ea1;
        lb += eb0 + eb1;
        aa = fmaf(ea0, y2.x, fmaf(ea1, y2.y, aa));
        ab = fmaf(eb0, y2.x, fmaf(eb1, y2.y, ab));
    }

    g_P[(size_t)n*VV*MM + mo0 + t]       = aa / la;
    g_P[(size_t)n*VV*MM + mo0 + t + 128] = ab / lb;
}

// -------- reduce heads + beff -> out[m][v] --------
__global__ void reduce_kernel(float* __restrict__ out) {
    const int e = blockIdx.x * 256 + threadIdx.x;
    if (e >= VV*MM) return;
    const int v = e >> 10;
    const int m = e & 1023;
    float s = g_beff[v];
    #pragma unroll
    for (int n = 0; n < NHH; n++) s += g_P[(size_t)n*VV*MM + e];
    out[(size_t)m*VV + v] = s;
}

extern "C" void kernel_launch(void* const* d_in, const int* in_sizes, int n_in,
                              void* d_out, int out_size) {
    const float* x        = (const float*)d_in[0];
    const float* adjl     = (const float*)d_in[1];
    const float* var_emb  = (const float*)d_in[2];
    const float* temp_emb = (const float*)d_in[3];
    const float* mech_W   = (const float*)d_in[4];
    const float* mech_b   = (const float*)d_in[5];
    const float* ln_g     = (const float*)d_in[6];
    const float* ln_b     = (const float*)d_in[7];
    const float* Wq       = (const float*)d_in[8];
    const float* Wk       = (const float*)d_in[9];
    const float* Wv       = (const float*)d_in[10];
    const float* Wo       = (const float*)d_in[11];
    const float* bq       = (const float*)d_in[12];
    const float* bk       = (const float*)d_in[13];
    const float* bv       = (const float*)d_in[14];
    const float* bo       = (const float*)d_in[15];
    const float* out_W    = (const float*)d_in[16];
    const float* out_b    = (const float*)d_in[17];
    float* out = (float*)d_out;

    prelude_kernel<<<(VV*VV*LLP1 + KAB*HH + 255)/256, 256>>>(adjl, var_emb, temp_emb);
    split_w_kernel<<<NTILES, 256>>>(mech_W, Wq, Wk);
    build_weff_kernel<<<VV, 128>>>(Wo, bo, out_W, out_b);
    build_Wvy_kernel<<<dim3(VV, 4), 256>>>(Wv, bv);
    build_AB_kernel<<<dim3(VV, BB, 2), 256>>>(x);

    // causal z = AB @ Wc  -> Z1
    gemm4<2,KAB,true,false><<<dim3(8, VV), 256>>>(4, 0, T_WC, 0,
        nullptr, nullptr, nullptr, 0, 0, nullptr, 0);

    // mech layers: Z1 -> Z2 -> Z1 -> Z2
    gemm4<0,128,false,false><<<dim3(8, VV), 256>>>(0, 1, 0*8, 24, mech_b, ln_g, ln_b, 0, 0, nullptr, 0);
    gemm4<0,128,false,false><<<dim3(8, VV), 256>>>(1, 0, 1*8, 24, mech_b, ln_g, ln_b, 1, 0, nullptr, 0);
    gemm4<0,128,false,false><<<dim3(8, VV), 256>>>(0, 1, 2*8, 24, mech_b, ln_g, ln_b, 2, 0, nullptr, 0);

    // folded V path: Y8 = Z2 @ Wvy + cy
    y8_kernel<<<dim3(VV, BB), 256>>>();

    // Q and K projections from Z2 in ONE launch (z=0 -> Qb, z=1 -> Kb)
    gemm4<1,128,false,true><<<dim3(8, VV, 2), 256>>>(1, 2, T_Q, 8, bq, nullptr, nullptr, 0,
                                                     T_K, bk, 3);

    // attention partials per head (2 queries/thread)
    attn4_kernel<<<dim3(NHH, VV, BB), 128>>>();

    // sum heads + bias -> out
    reduce_kernel<<<(VV*MM + 255)/256, 256>>>(out);
}

// round 14
// speedup vs baseline: 1.7392x; 1.2453x over previous
#include <cuda_runtime.h>
#include <cuda_bf16.h>
#include <math.h>
#include <stdint.h>

#define BB  4
#define SS  256
#define VV  64
#define HH  128
#define NHH 8
#define DHH 16
#define NLL 3
#define LLP1 11
#define MM  (BB*SS)   // 1024
#define KAB 96        // padded causal K (64 A + 11 Bl + 21 zero)

// weight-tile arena: tiles of [128 n][16 kperm] bf16 (2048 bf16 = 256 uint4 each)
#define T_Q  1536
#define T_K  2048
#define T_WC 2560
#define NTILES 2566

// -------- device scratch (static; allocation-free) --------
__device__ float g_adj[VV*VV*LLP1];
__device__ float g_Z1[(size_t)VV*MM*HH];
__device__ float g_Z2[(size_t)VV*MM*HH];
__device__ float g_Qb[(size_t)VV*MM*HH];
__device__ float g_Kb[(size_t)VV*MM*HH];
__device__ float g_AB[(size_t)VV*KAB*MM];   // k-major: [v][k][m]
__device__ float g_Wc[KAB*HH];
__device__ float g_weff[VV*HH];
__device__ float g_beff[VV];
__device__ float g_Wvy[(size_t)VV*HH*NHH];  // [v][h*8+n]
__device__ float g_cy[VV*NHH];
__device__ float g_Y8[(size_t)NHH*VV*MM];   // [n][v][m]
__device__ float g_P[(size_t)NHH*VV*MM];    // per-head partials [n][v][m]
__device__ __nv_bfloat16 g_Whi[(size_t)NTILES*2048];
__device__ __nv_bfloat16 g_Wlo[(size_t)NTILES*2048];

__device__ __forceinline__ float* buf_sel(int s) {
    return (s == 0) ? g_Z1 : (s == 1) ? g_Z2 : (s == 2) ? g_Qb
         : (s == 3) ? g_Kb : g_AB;
}

__device__ __forceinline__ void cpasync16(uint32_t saddr, const void* g) {
    asm volatile("cp.async.cg.shared.global [%0], [%1], 16;\n" :: "r"(saddr), "l"(g));
}

// pack two fp32 -> bf16x2 (x0 in low half = lower-k element)
__device__ __forceinline__ uint32_t cvt_pack(float x0, float x1) {
    uint32_t r;
    asm("cvt.rn.bf16x2.f32 %0, %1, %2;" : "=r"(r) : "f"(x1), "f"(x0));
    return r;
}
// hi/lo split of a pair
__device__ __forceinline__ void split_pair(float x0, float x1, uint32_t& h, uint32_t& l) {
    h = cvt_pack(x0, x1);
    float h0 = __uint_as_float(h << 16);
    float h1 = __uint_as_float(h & 0xffff0000u);
    l = cvt_pack(x0 - h0, x1 - h1);
}

__device__ __forceinline__ void mma_bf16(float* d, const uint32_t* a, uint32_t b0, uint32_t b1) {
    asm volatile("mma.sync.aligned.m16n8k16.row.col.f32.bf16.bf16.f32 "
        "{%0,%1,%2,%3}, {%4,%5,%6,%7}, {%8,%9}, {%0,%1,%2,%3};"
        : "+f"(d[0]), "+f"(d[1]), "+f"(d[2]), "+f"(d[3])
        : "r"(a[0]), "r"(a[1]), "r"(a[2]), "r"(a[3]), "r"(b0), "r"(b1));
}

// k-permutation: perm[4*tig+j] = 2tig + (j&1) + (j>=2)*8
__device__ __forceinline__ int kperm(int p) {
    return 2*(p >> 2) + (p & 1) + ((p >> 1) & 1)*8;
}
// inverse: position of k within the 16-block
__device__ __forceinline__ int kinv(int k) {
    return (((k & 7) >> 1) << 2) + (k & 1) + ((k >> 3) << 1);
}

// -------- fused: sigmoid(adjacency) + build Wc[96][128] --------
__global__ void prelude_kernel(const float* __restrict__ logits,
                               const float* __restrict__ var_emb,
                               const float* __restrict__ temp_emb) {
    int idx = blockIdx.x * 256 + threadIdx.x;
    if (idx < VV*VV*LLP1) {
        float v = logits[idx];
        g_adj[idx] = 1.f / (1.f + expf(-v));
    }
    int idx2 = idx - VV*VV*LLP1;
    if (idx2 >= 0 && idx2 < KAB*HH) {
        int r = idx2 >> 7, h = idx2 & 127;
        float val = 0.f;
        if (r < VV) val = var_emb[r*HH + h];
        else if (r < VV + LLP1) val = temp_emb[(r - VV)*HH + h];
        g_Wc[idx2] = val;
    }
}

// -------- split all weights into bf16 hi/lo arena with k-permutation --------
__global__ void __launch_bounds__(256) split_w_kernel(const float* __restrict__ mech_W,
                                                      const float* __restrict__ Wq,
                                                      const float* __restrict__ Wk) {
    const int t = blockIdx.x;
    const int tid = threadIdx.x;
    const float* src;
    if (t < T_Q)       src = mech_W + (size_t)(t >> 3)*16384 + (size_t)(t & 7)*2048;
    else if (t < T_K)  src = Wq + (size_t)((t - T_Q) >> 3)*16384 + (size_t)(t & 7)*2048;
    else if (t < T_WC) src = Wk + (size_t)((t - T_K) >> 3)*16384 + (size_t)(t & 7)*2048;
    else               src = g_Wc + (size_t)(t - T_WC)*2048;

    __shared__ float ws[16][129];
    {
        int e = tid*8;
        int r = e >> 7, c = e & 127;
        float4 a = *(const float4*)(src + e);
        float4 b = *(const float4*)(src + e + 4);
        ws[r][c+0]=a.x; ws[r][c+1]=a.y; ws[r][c+2]=a.z; ws[r][c+3]=a.w;
        ws[r][c+4]=b.x; ws[r][c+5]=b.y; ws[r][c+6]=b.z; ws[r][c+7]=b.w;
    }
    __syncthreads();

    const int n  = tid >> 1;
    const int p0 = (tid & 1)*8;
    uint32_t hw[4], lw[4];
    #pragma unroll
    for (int jp = 0; jp < 4; jp++) {
        float x0 = ws[kperm(p0 + jp*2 + 0)][n];
        float x1 = ws[kperm(p0 + jp*2 + 1)][n];
        split_pair(x0, x1, hw[jp], lw[jp]);
    }
    ((uint4*)g_Whi)[(size_t)t*256 + tid] = make_uint4(hw[0], hw[1], hw[2], hw[3]);
    ((uint4*)g_Wlo)[(size_t)t*256 + tid] = make_uint4(lw[0], lw[1], lw[2], lw[3]);
}

// -------- fold O-proj into output head --------
__global__ void build_weff_kernel(const float* __restrict__ Wo,
                                  const float* __restrict__ bo,
                                  const float* __restrict__ outW,
                                  const float* __restrict__ outb) {
    const int v = blockIdx.x;
    const int h = threadIdx.x;   // 128
    __shared__ float sw[HH];
    __shared__ float red[HH];
    sw[h] = outW[v*HH + h];
    __syncthreads();
    const float* wp = Wo + ((size_t)v*HH + h)*HH;
    float s = 0.f;
    #pragma unroll 8
    for (int k = 0; k < HH; k++) s = fmaf(wp[k], sw[k], s);
    g_weff[v*HH + h] = s;
    red[h] = bo[v*HH + h] * sw[h];
    __syncthreads();
    #pragma unroll
    for (int o = 64; o > 0; o >>= 1) {
        if (h < o) red[h] += red[h + o];
        __syncthreads();
    }
    if (h == 0) g_beff[v] = red[0] + outb[v];
}

// -------- fold V-proj through the head --------
__global__ void build_Wvy_kernel(const float* __restrict__ Wv,
                                 const float* __restrict__ bv) {
    const int v = blockIdx.x;
    const int q = blockIdx.y;
    const int t = threadIdx.x;   // 256
    __shared__ float wsh[HH];
    if (t < HH) wsh[t] = g_weff[v*HH + t];
    __syncthreads();
    const int e = q*256 + t;     // e = h*8 + n
    const int h = e >> 3, n = e & 7;
    const float* wp = Wv + ((size_t)v*HH + h)*HH + n*DHH;
    const float* gp = wsh + n*DHH;
    float4 x0 = *(const float4*)(wp),   x1 = *(const float4*)(wp+4);
    float4 x2 = *(const float4*)(wp+8), x3 = *(const float4*)(wp+12);
    float4 g0 = *(const float4*)(gp),   g1 = *(const float4*)(gp+4);
    float4 g2 = *(const float4*)(gp+8), g3 = *(const float4*)(gp+12);
    float s0 = x0.x*g0.x + x0.y*g0.y + x0.z*g0.z + x0.w*g0.w;
    float s1 = x1.x*g1.x + x1.y*g1.y + x1.z*g1.z + x1.w*g1.w;
    float s2 = x2.x*g2.x + x2.y*g2.y + x2.z*g2.z + x2.w*g2.w;
    float s3 = x3.x*g3.x + x3.y*g3.y + x3.z*g3.z + x3.w*g3.w;
    g_Wvy[(size_t)v*HH*NHH + e] = (s0 + s1) + (s2 + s3);
    if (q == 0 && t < NHH) {
        const float* bp = bv + (size_t)v*HH + t*DHH;
        const float* gp2 = wsh + t*DHH;
        float s = 0.f;
        #pragma unroll
        for (int d = 0; d < DHH; d++) s = fmaf(bp[d], gp2[d], s);
        g_cy[v*NHH + t] = s;
    }
}

// -------- stage AB_T[i][k][m] --------
__global__ void __launch_bounds__(256) build_AB_kernel(const float* __restrict__ x) {
    const int i  = blockIdx.x;
    const int b  = blockIdx.y;
    const int t0 = blockIdx.z * 128;
    __shared__ float xsh[VV][140];
    __shared__ float adjs[VV][12];
    __shared__ float blsh[LLP1][129];
    const int tid = threadIdx.x;     // 256

    for (int f = tid; f < 138*16; f += 256) {
        int j = f >> 4, s4 = f & 15;
        int t = t0 - 10 + j;
        float4 xv = make_float4(0.f, 0.f, 0.f, 0.f);
        if (t >= 0) xv = *(const float4*)(x + ((size_t)(b*SS + t))*VV + s4*4);
        xsh[s4*4+0][j] = xv.x;
        xsh[s4*4+1][j] = xv.y;
        xsh[s4*4+2][j] = xv.z;
        xsh[s4*4+3][j] = xv.w;
    }
    for (int f = tid; f < VV*LLP1; f += 256) {
        int s = f / LLP1, l = f - s*LLP1;
        adjs[s][l] = g_adj[((size_t)s*VV + i)*LLP1 + l];
    }
    __syncthreads();

    const int t    = tid & 127;
    const int half = tid >> 7;
    const int j0 = t + 10;
    float bl[LLP1];
    #pragma unroll
    for (int l = 0; l < LLP1; l++) bl[l] = 0.f;

    float* ABi = g_AB + (size_t)i*KAB*MM + b*SS + t0;
    const int s0 = half*32;
    #pragma unroll 2
    for (int s = s0; s < s0 + 32; s++) {
        const float* xr = xsh[s];
        const float* ar = adjs[s];
        float a = 0.f;
        #pragma unroll
        for (int l = 0; l < LLP1; l++) {
            float p = xr[j0 - l] * ar[l];
            a += p;
            bl[l] += p;
        }
        ABi[(size_t)s*MM + t] = a;
    }
    if (half == 1) {
        #pragma unroll
        for (int l = 0; l < LLP1; l++) blsh[l][t] = bl[l];
    }
    __syncthreads();
    if (half == 0) {
        #pragma unroll
        for (int l = 0; l < LLP1; l++) ABi[(size_t)(VV + l)*MM + t] = bl[l] + blsh[l][t];
    } else {
        #pragma unroll
        for (int r = VV + LLP1; r < KAB; r++) ABi[(size_t)r*MM + t] = 0.f;
    }
}

// -------- tensor-core GEMM: 128x128 tile, KT=16, bf16-split x3 --------
template<int MODE, int KDIM, bool XT, bool DUAL>
__global__ void __launch_bounds__(256, 2)
gemm4(int src, int dst, int tbase, int tstride,
      const float* __restrict__ ball,
      const float* __restrict__ lng, const float* __restrict__ lnb, int li,
      int tbase2, const float* __restrict__ ball2, int dst2)
{
    constexpr int NK = KDIM / 16;
    __shared__ float As[2][16][160];
    __shared__ __nv_bfloat16 Bh[2][128][16];
    __shared__ __nv_bfloat16 Bl[2][128][16];
    __shared__ float sBias[128], sG[128], sBt[128];
    const uint32_t As_u = (uint32_t)__cvta_generic_to_shared(&As[0][0][0]);
    const uint32_t Bh_u = (uint32_t)__cvta_generic_to_shared(&Bh[0][0][0]);
    const uint32_t Bl_u = (uint32_t)__cvta_generic_to_shared(&Bl[0][0][0]);

    const int v   = blockIdx.y;
    const int m0  = blockIdx.x * 128;
    const int tid = threadIdx.x;
    const int w = tid >> 5, lane = tid & 31;
    const int g = lane >> 2, tig = lane & 3;

    const float* ballX = ball;
    int dstX = dst, tbX = tbase;
    if (DUAL && blockIdx.z == 1) { ballX = ball2; dstX = dst2; tbX = tbase2; }
    const int tb = tbX + v*tstride;

    const float* Xb = buf_sel(src);
    const float* Xv = XT ? (Xb + (size_t)v*KDIM*MM)
                         : (Xb + ((size_t)v*MM + m0)*HH);

    if (MODE < 2 && tid < 128)
        sBias[tid] = (MODE == 0) ? ballX[((size_t)v*NLL + li)*HH + tid]
                                 : ballX[(size_t)v*HH + tid];
    if (MODE == 0 && tid < 128) {
        sG[tid]  = lng[((size_t)v*NLL + li)*HH + tid];
        sBt[tid] = lnb[((size_t)v*NLL + li)*HH + tid];
    }

    float d[16][4];
    #pragma unroll
    for (int f = 0; f < 16; f++) { d[f][0]=0.f; d[f][1]=0.f; d[f][2]=0.f; d[f][3]=0.f; }

    float4 pa0, pa1;
    const int am = tid >> 1, kseg = tid & 1;
    const int xr = tid >> 4, xseg = tid & 15;

    auto issueA = [&](int kt, int buf) {
        if (XT) {
            const float* gp = Xv + (size_t)(kt*16 + xr)*MM + m0 + xseg*8;
            uint32_t dsa = As_u + (uint32_t)((buf*16*160 + kinv(xr)*160 + xseg*8) * 4);
            cpasync16(dsa, gp);
            cpasync16(dsa + 16, gp + 4);
        } else {
            const float* gp = Xv + (size_t)am*HH + kt*16 + kseg*8;
            pa0 = *(const float4*)gp;
            pa1 = *(const float4*)(gp + 4);
        }
    };
    auto storeA = [&](int buf) {
        if (!XT) {
            float* base = &As[buf][0][0] + am;
            const int kb2 = kseg*2;
            base[(0 + kb2)*160] = pa0.x;  base[(1 + kb2)*160]  = pa0.y;
            base[(4 + kb2)*160] = pa0.z;  base[(5 + kb2)*160]  = pa0.w;
            base[(8 + kb2)*160] = pa1.x;  base[(9 + kb2)*160]  = pa1.y;
            base[(12 + kb2)*160] = pa1.z; base[(13 + kb2)*160] = pa1.w;
        }
    };
    auto issueB = [&](int kt, int buf) {
        const char* sh = (const char*)g_Whi + (size_t)(tb + kt)*4096 + tid*16;
        const char* sl = (const char*)g_Wlo + (size_t)(tb + kt)*4096 + tid*16;
        cpasync16(Bh_u + (uint32_t)(buf*4096 + tid*16), sh);
        cpasync16(Bl_u + (uint32_t)(buf*4096 + tid*16), sl);
    };

    issueA(0, 0);
    issueB(0, 0);
    storeA(0);
    asm volatile("cp.async.commit_group;\n");
    asm volatile("cp.async.wait_group 0;\n" ::: "memory");
    __syncthreads();

    const int r0 = w*16 + g;

    #pragma unroll 1
    for (int kt = 0; kt < NK; kt++) {
        const int cur = kt & 1, nxt = cur ^ 1;
        if (kt + 1 < NK) {
            issueA(kt + 1, nxt);
            issueB(kt + 1, nxt);
            asm volatile("cp.async.commit_group;\n");
        }

        float af[8];
        #pragma unroll
        for (int j = 0; j < 4; j++) {
            af[j]     = As[cur][4*tig + j][r0];
            af[4 + j] = As[cur][4*tig + j][r0 + 8];
        }
        uint32_t ah[4], al[4];
        split_pair(af[0], af[1], ah[0], al[0]);
        split_pair(af[4], af[5], ah[1], al[1]);
        split_pair(af[2], af[3], ah[2], al[2]);
        split_pair(af[6], af[7], ah[3], al[3]);

        #pragma unroll
        for (int f = 0; f < 16; f++) {
            const int n = f*8 + g;
            uint2 bhv = *(const uint2*)&Bh[cur][n][4*tig];
            uint2 blv = *(const uint2*)&Bl[cur][n][4*tig];
            mma_bf16(d[f], ah, bhv.x, bhv.y);
            mma_bf16(d[f], ah, blv.x, blv.y);
            mma_bf16(d[f], al, bhv.x, bhv.y);
        }

        if (kt + 1 < NK) {
            storeA(nxt);
            asm volatile("cp.async.wait_group 0;\n" ::: "memory");
            __syncthreads();
        }
    }

    if (MODE < 2) {
        #pragma unroll
        for (int f = 0; f < 16; f++) {
            float b0 = sBias[f*8 + 2*tig];
            float b1 = sBias[f*8 + 2*tig + 1];
            d[f][0] += b0; d[f][1] += b1;
            d[f][2] += b0; d[f][3] += b1;
        }
    }

    if (MODE == 0) {
        float s1a = 0.f, s2a = 0.f, s1b = 0.f, s2b = 0.f;
        #pragma unroll
        for (int f = 0; f < 16; f++) {
            s1a += d[f][0] + d[f][1];
            s2a += d[f][0]*d[f][0] + d[f][1]*d[f][1];
            s1b += d[f][2] + d[f][3];
            s2b += d[f][2]*d[f][2] + d[f][3]*d[f][3];
        }
        #pragma unroll
        for (int o = 1; o <= 2; o <<= 1) {
            s1a += __shfl_xor_sync(0xffffffffu, s1a, o);
            s2a += __shfl_xor_sync(0xffffffffu, s2a, o);
            s1b += __shfl_xor_sync(0xffffffffu, s1b, o);
            s2b += __shfl_xor_sync(0xffffffffu, s2b, o);
        }
        float mua  = s1a*(1.f/128.f), mub = s1b*(1.f/128.f);
        float inva = rsqrtf(s2a*(1.f/128.f) - mua*mua + 1e-5f);
        float invb = rsqrtf(s2b*(1.f/128.f) - mub*mub + 1e-5f);
        #pragma unroll
        for (int f = 0; f < 16; f++) {
            const int c0 = f*8 + 2*tig;
            float g0 = sG[c0], g1 = sG[c0+1], t0v = sBt[c0], t1v = sBt[c0+1];
            float x;
            x = (d[f][0] - mua)*inva*g0 + t0v;
            d[f][0] = 0.5f*x*(1.f + erff(x*0.70710678118654752f));
            x = (d[f][1] - mua)*inva*g1 + t1v;
            d[f][1] = 0.5f*x*(1.f + erff(x*0.70710678118654752f));
            x = (d[f][2] - mub)*invb*g0 + t0v;
            d[f][2] = 0.5f*x*(1.f + erff(x*0.70710678118654752f));
            x = (d[f][3] - mub)*invb*g1 + t1v;
            d[f][3] = 0.5f*x*(1.f + erff(x*0.70710678118654752f));
        }
    }

    float* Yv = buf_sel(dstX) + ((size_t)v*MM + m0)*HH;
    #pragma unroll
    for (int f = 0; f < 16; f++) {
        const int c0 = f*8 + 2*tig;
        *(float2*)(Yv + (size_t)r0*HH + c0)       = make_float2(d[f][0], d[f][1]);
        *(float2*)(Yv + (size_t)(r0 + 8)*HH + c0) = make_float2(d[f][2], d[f][3]);
    }
}

// -------- y8: Y8[n][v][m] = Z2[v,m,:].Wvy[v,:,n] + cy[v,n] --------
__global__ void __launch_bounds__(256) y8_kernel() {
    const int v = blockIdx.x, b = blockIdx.y;
    __shared__ __align__(16) float wv_sh[HH][NHH];
    const int t = threadIdx.x;
    {
        const float4* src = (const float4*)(g_Wvy + (size_t)v*HH*NHH);
        float4* dstp = (float4*)&wv_sh[0][0];
        dstp[t] = src[t];
    }
    __syncthreads();

    const float* zr = g_Z2 + ((size_t)v*MM + (size_t)b*SS + t)*HH;
    float ya[NHH];
    #pragma unroll
    for (int n = 0; n < NHH; n++) ya[n] = g_cy[v*NHH + n];
    #pragma unroll 4
    for (int h0 = 0; h0 < HH; h0 += 4) {
        float4 z = *(const float4*)(zr + h0);
        const float zz[4] = {z.x, z.y, z.z, z.w};
        #pragma unroll
        for (int hi = 0; hi < 4; hi++) {
            float4 w0 = *(const float4*)&wv_sh[h0 + hi][0];
            float4 w1 = *(const float4*)&wv_sh[h0 + hi][4];
            ya[0] = fmaf(zz[hi], w0.x, ya[0]);
            ya[1] = fmaf(zz[hi], w0.y, ya[1]);
            ya[2] = fmaf(zz[hi], w0.z, ya[2]);
            ya[3] = fmaf(zz[hi], w0.w, ya[3]);
            ya[4] = fmaf(zz[hi], w1.x, ya[4]);
            ya[5] = fmaf(zz[hi], w1.y, ya[5]);
            ya[6] = fmaf(zz[hi], w1.z, ya[6]);
            ya[7] = fmaf(zz[hi], w1.w, ya[7]);
        }
    }
    const size_t mo = (size_t)v*MM + (size_t)b*SS + t;
    #pragma unroll
    for (int n = 0; n < NHH; n++) g_Y8[(size_t)n*VV*MM + mo] = ya[n];
}

// -------- tensor-core attention: per-(n,v,b) block, bf16-split QK via MMA --------
// S = (Q*0.25)·K^T using 3-term split; exp + scalar-y accumulate; row-reduce over quad.
__global__ void __launch_bounds__(256) attn5_kernel() {
    const int n = blockIdx.x, v = blockIdx.y, b = blockIdx.z;
    __shared__ uint32_t Qh[SS][8], Ql[SS][8];   // 8 KB each (bf16x2, kperm order)
    __shared__ uint32_t Kh[SS][8], Kl[SS][8];
    __shared__ __align__(8) float ys[SS];

    const int t = threadIdx.x;   // 256
    const size_t base = ((size_t)v*MM + (size_t)b*SS)*HH + n*DHH;
    const size_t mo0 = (size_t)v*MM + (size_t)b*SS;

    // stage: thread t owns Q row t and K row t (16 features each)
    {
        const float* Qp = g_Qb + base + (size_t)t*HH;
        float4 q0 = *(const float4*)(Qp),     q1 = *(const float4*)(Qp + 4);
        float4 q2 = *(const float4*)(Qp + 8), q3 = *(const float4*)(Qp + 12);
        float qv[16] = {q0.x*0.25f,q0.y*0.25f,q0.z*0.25f,q0.w*0.25f,
                        q1.x*0.25f,q1.y*0.25f,q1.z*0.25f,q1.w*0.25f,
                        q2.x*0.25f,q2.y*0.25f,q2.z*0.25f,q2.w*0.25f,
                        q3.x*0.25f,q3.y*0.25f,q3.z*0.25f,q3.w*0.25f};
        uint32_t hh[8], ll[8];
        #pragma unroll
        for (int tt = 0; tt < 4; tt++) {
            split_pair(qv[2*tt],     qv[2*tt+1], hh[2*tt],   ll[2*tt]);
            split_pair(qv[2*tt+8],   qv[2*tt+9], hh[2*tt+1], ll[2*tt+1]);
        }
        *(uint4*)&Qh[t][0] = make_uint4(hh[0],hh[1],hh[2],hh[3]);
        *(uint4*)&Qh[t][4] = make_uint4(hh[4],hh[5],hh[6],hh[7]);
        *(uint4*)&Ql[t][0] = make_uint4(ll[0],ll[1],ll[2],ll[3]);
        *(uint4*)&Ql[t][4] = make_uint4(ll[4],ll[5],ll[6],ll[7]);

        const float* Kp = g_Kb + base + (size_t)t*HH;
        float4 k0 = *(const float4*)(Kp),     k1 = *(const float4*)(Kp + 4);
        float4 k2 = *(const float4*)(Kp + 8), k3 = *(const float4*)(Kp + 12);
        float kv[16] = {k0.x,k0.y,k0.z,k0.w, k1.x,k1.y,k1.z,k1.w,
                        k2.x,k2.y,k2.z,k2.w, k3.x,k3.y,k3.z,k3.w};
        #pragma unroll
        for (int tt = 0; tt < 4; tt++) {
            split_pair(kv[2*tt],     kv[2*tt+1], hh[2*tt],   ll[2*tt]);
            split_pair(kv[2*tt+8],   kv[2*tt+9], hh[2*tt+1], ll[2*tt+1]);
        }
        *(uint4*)&Kh[t][0] = make_uint4(hh[0],hh[1],hh[2],hh[3]);
        *(uint4*)&Kh[t][4] = make_uint4(hh[4],hh[5],hh[6],hh[7]);
        *(uint4*)&Kl[t][0] = make_uint4(ll[0],ll[1],ll[2],ll[3]);
        *(uint4*)&Kl[t][4] = make_uint4(ll[4],ll[5],ll[6],ll[7]);

        ys[t] = g_Y8[(size_t)n*VV*MM + mo0 + t];
    }
    __syncthreads();

    const int w = t >> 5, lane = t & 31;
    const int g = lane >> 2, tig = lane & 3;

    #pragma unroll 1
    for (int rb = 0; rb < 2; rb++) {
        const int rw = rb*128 + w*16 + g;
        uint2 qh01 = *(const uint2*)&Qh[rw][2*tig];
        uint2 qh23 = *(const uint2*)&Qh[rw + 8][2*tig];
        uint2 ql01 = *(const uint2*)&Ql[rw][2*tig];
        uint2 ql23 = *(const uint2*)&Ql[rw + 8][2*tig];
        uint32_t ah[4] = {qh01.x, qh23.x, qh01.y, qh23.y};
        uint32_t al[4] = {ql01.x, ql23.x, ql01.y, ql23.y};

        float accA = 0.f, accB = 0.f, lA = 0.f, lB = 0.f;

        #pragma unroll 8
        for (int jt = 0; jt < 32; jt++) {
            const int kr = jt*8 + g;
            uint2 bh = *(const uint2*)&Kh[kr][2*tig];
            uint2 bl = *(const uint2*)&Kl[kr][2*tig];
            float dd[4] = {0.f, 0.f, 0.f, 0.f};
            mma_bf16(dd, ah, bh.x, bh.y);
            mma_bf16(dd, al, bh.x, bh.y);
            mma_bf16(dd, ah, bl.x, bl.y);
            float p0 = __expf(dd[0]);
            float p1 = __expf(dd[1]);
            float p2 = __expf(dd[2]);
            float p3 = __expf(dd[3]);
            float2 yv = *(const float2*)&ys[jt*8 + 2*tig];
            accA = fmaf(p0, yv.x, fmaf(p1, yv.y, accA));
            accB = fmaf(p2, yv.x, fmaf(p3, yv.y, accB));
            lA += p0 + p1;
            lB += p2 + p3;
        }

        #pragma unroll
        for (int o = 1; o <= 2; o <<= 1) {
            accA += __shfl_xor_sync(0xffffffffu, accA, o);
            accB += __shfl_xor_sync(0xffffffffu, accB, o);
            lA   += __shfl_xor_sync(0xffffffffu, lA, o);
            lB   += __shfl_xor_sync(0xffffffffu, lB, o);
        }
        if (tig == 0) {
            g_P[(size_t)n*VV*MM + mo0 + rw]     = accA / lA;
            g_P[(size_t)n*VV*MM + mo0 + rw + 8] = accB / lB;
        }
    }
}

// -------- reduce heads + beff -> out[m][v] --------
__global__ void reduce_kernel(float* __restrict__ out) {
    const int e = blockIdx.x * 256 + threadIdx.x;
    if (e >= VV*MM) return;
    const int v = e >> 10;
    const int m = e & 1023;
    float s = g_beff[v];
    #pragma unroll
    for (int n = 0; n < NHH; n++) s += g_P[(size_t)n*VV*MM + e];
    out[(size_t)m*VV + v] = s;
}

extern "C" void kernel_launch(void* const* d_in, const int* in_sizes, int n_in,
                              void* d_out, int out_size) {
    const float* x        = (const float*)d_in[0];
    const float* adjl     = (const float*)d_in[1];
    const float* var_emb  = (const float*)d_in[2];
    const float* temp_emb = (const float*)d_in[3];
    const float* mech_W   = (const float*)d_in[4];
    const float* mech_b   = (const float*)d_in[5];
    const float* ln_g     = (const float*)d_in[6];
    const float* ln_b     = (const float*)d_in[7];
    const float* Wq       = (const float*)d_in[8];
    const float* Wk       = (const float*)d_in[9];
    const float* Wv       = (const float*)d_in[10];
    const float* Wo       = (const float*)d_in[11];
    const float* bq       = (const float*)d_in[12];
    const float* bk       = (const float*)d_in[13];
    const float* bv       = (const float*)d_in[14];
    const float* bo       = (const float*)d_in[15];
    const float* out_W    = (const float*)d_in[16];
    const float* out_b    = (const float*)d_in[17];
    float* out = (float*)d_out;

    prelude_kernel<<<(VV*VV*LLP1 + KAB*HH + 255)/256, 256>>>(adjl, var_emb, temp_emb);
    split_w_kernel<<<NTILES, 256>>>(mech_W, Wq, Wk);
    build_weff_kernel<<<VV, 128>>>(Wo, bo, out_W, out_b);
    build_Wvy_kernel<<<dim3(VV, 4), 256>>>(Wv, bv);
    build_AB_kernel<<<dim3(VV, BB, 2), 256>>>(x);

    // causal z = AB @ Wc  -> Z1
    gemm4<2,KAB,true,false><<<dim3(8, VV), 256>>>(4, 0, T_WC, 0,
        nullptr, nullptr, nullptr, 0, 0, nullptr, 0);

    // mech layers: Z1 -> Z2 -> Z1 -> Z2
    gemm4<0,128,false,false><<<dim3(8, VV), 256>>>(0, 1, 0*8, 24, mech_b, ln_g, ln_b, 0, 0, nullptr, 0);
    gemm4<0,128,false,false><<<dim3(8, VV), 256>>>(1, 0, 1*8, 24, mech_b, ln_g, ln_b, 1, 0, nullptr, 0);
    gemm4<0,128,false,false><<<dim3(8, VV), 256>>>(0, 1, 2*8, 24, mech_b, ln_g, ln_b, 2, 0, nullptr, 0);

    // folded V path: Y8 = Z2 @ Wvy + cy
    y8_kernel<<<dim3(VV, BB), 256>>>();

    // Q and K projections from Z2 in ONE launch (z=0 -> Qb, z=1 -> Kb)
    gemm4<1,128,false,true><<<dim3(8, VV, 2), 256>>>(1, 2, T_Q, 8, bq, nullptr, nullptr, 0,
                                                     T_K, bk, 3);

    // tensor-core attention partials per head
    attn5_kernel<<<dim3(NHH, VV, BB), 256>>>();

    // sum heads + bias -> out
    reduce_kernel<<<(VV*MM + 255)/256, 256>>>(out);
}